// round 10
// baseline (speedup 1.0000x reference)
#include <cuda_runtime.h>
#include <math_constants.h>

// ---------------------------------------------------------------------------
// Problem constants
// ---------------------------------------------------------------------------
#define BATCH 4
#define NPTS  1024
#define CIN   768
#define KNN   20
#define HDIM  1152    // 512 + 256 + 128 + 256
#define PCH   32      // pooling chunks
#define EPS   1e-5f

// ---------------------------------------------------------------------------
// Scratch (device globals; no allocation allowed)
// ---------------------------------------------------------------------------
__device__ float g_XT [BATCH * NPTS * CIN];     // x transposed: (B, N, C)
__device__ float g_G  [BATCH * NPTS * NPTS];    // gram matrix
__device__ float g_diag[BATCH * NPTS];          // gram diagonal
__device__ int   g_idx[BATCH * NPTS * KNN];     // knn indices
__device__ float g_U  [BATCH * NPTS * 512];     // W_left  @ x
__device__ float g_V  [BATCH * NPTS * 512];     // W_right @ x
__device__ float g_H  [BATCH * NPTS * HDIM];    // concat(x1,x2,x3,x4)
__device__ float g_H5 [BATCH * NPTS * 1024];    // conv5 output
__device__ float g_pmax[BATCH * PCH * 1024];
__device__ float g_psum[BATCH * PCH * 1024];
__device__ float g_pool[BATCH * 2048];
__device__ float g_z   [BATCH * 512];

// ---------------------------------------------------------------------------
// Packed f32x2 helpers: each lane is an independent rn-rounded fp32 FMA
// -> per-output bit-identical to the scalar FFMA chain with the same k order.
// ---------------------------------------------------------------------------
static __device__ __forceinline__ unsigned long long pk2(float x, float y) {
    unsigned long long r;
    asm("mov.b64 %0, {%1, %2};" : "=l"(r) : "f"(x), "f"(y));
    return r;
}
static __device__ __forceinline__ void upk2(unsigned long long v, float& x, float& y) {
    asm("mov.b64 {%0, %1}, %2;" : "=f"(x), "=f"(y) : "l"(v));
}
static __device__ __forceinline__ void ffma2(unsigned long long& d,
                                             unsigned long long a,
                                             unsigned long long b) {
    asm("fma.rn.f32x2 %0, %1, %2, %0;" : "+l"(d) : "l"(a), "l"(b));
}

// ---------------------------------------------------------------------------
// Transpose: x (B, C, N) -> XT (B, N, C)
// ---------------------------------------------------------------------------
__global__ void transpose_kernel(const float* __restrict__ x, float* __restrict__ xt) {
    __shared__ float tile[32][33];
    int b  = blockIdx.z;
    int c0 = blockIdx.y * 32;
    int n0 = blockIdx.x * 32;
    const float* xb  = x  + (long)b * CIN * NPTS;
    float*       xtb = xt + (long)b * NPTS * CIN;
    int tx = threadIdx.x, ty = threadIdx.y;            // 32 x 8
#pragma unroll
    for (int i = 0; i < 32; i += 8)
        tile[ty + i][tx] = xb[(long)(c0 + ty + i) * NPTS + n0 + tx];
    __syncthreads();
#pragma unroll
    for (int i = 0; i < 32; i += 8)
        xtb[(long)(n0 + ty + i) * CIN + c0 + tx] = tile[tx][ty + i];
}

// ---------------------------------------------------------------------------
// Tiled SGEMM (dual-source N split) with packed fma.rn.f32x2:
//   blocks with nb0 <  N1 compute C1 = A * B1^T
//   blocks with nb0 >= N1 compute C2 = A * B2^T
// 128x128 tiles, 256 threads, per thread 8 rows x 8 cols held as
// 8 x 4 u64 accumulators over COLUMN PAIRS:
//   acc[r][p] = { C[r][c2p], C[r][c2p+1] }
// B's u64 operand {b_c, b_c+1} comes naturally from contiguous smem
// (conflict-free tx*4 pattern); A is duplicated {a,a} in smem, and A loads
// are half-warp broadcast so the dup costs no extra wavefronts.
// Per k-step: 6 LDS.128 + 32 FFMA2 (=64 FMA lanes) -> FMA-pipe bound at 2x
// the scalar FFMA rate. Sequential k accumulation -> bit-identical numerics.
// sym != 0: only blocks bx <= by computed (Gram symmetry; mirrored later).
// Requirements: M % 128 == 0, N % 128 == 0 (and N1 % 128 == 0), K % 16 == 0
// ---------------------------------------------------------------------------
#define BM 128
#define BN 128
#define BK 16

__global__ void __launch_bounds__(256, 2)
gemm_nt(const float* __restrict__ A, int lda, long strideA,
        const float* __restrict__ B1, const float* __restrict__ B2,
        int ldb, long strideB,
        float* __restrict__ C1, float* __restrict__ C2,
        int ldc, long strideC,
        int N1, int K,
        const float* __restrict__ bn, int bnN, int sym)
{
    if (sym && (int)blockIdx.x > (int)blockIdx.y) return;

    __shared__ __align__(16) float As2[2][BK][2 * BM];   // dup {a,a}: 32 KB
    __shared__ __align__(16) float Bs [2][BK][BN];       // 16 KB  (total 48 KB)

    const int bz = blockIdx.z;
    const int m0 = blockIdx.y * BM;
    const int nb0 = blockIdx.x * BN;

    const float* Bsel;
    float*       Csel;
    int n0;
    if (nb0 < N1) { Bsel = B1; Csel = C1; n0 = nb0; }
    else          { Bsel = B2; Csel = C2; n0 = nb0 - N1; }

    const float* Ab = A    + (long)bz * strideA;
    const float* Bb = Bsel + (long)bz * strideB;
    float*       Cb = Csel + (long)bz * strideC;

    const int tid = threadIdx.x;
    // loader mapping: rows lr and lr+64, 4 k-values each
    const int lr = tid >> 2;            // 0..63
    const int lc = (tid & 3) * 4;       // 0,4,8,12
    // compute mapping: 16x16 thread grid
    const int ty = tid >> 4;            // 0..15  -> rows ty*4..+3 and +64
    const int tx = tid & 15;            // 0..15  -> cols tx*4..+3 and +64

    unsigned long long acc[8][4];       // 8 rows x 4 col-pairs
#pragma unroll
    for (int i = 0; i < 8; i++)
#pragma unroll
        for (int j = 0; j < 4; j++) acc[i][j] = 0ull;

    const int nTiles = K / BK;
    float4 pa0, pa1, pb0, pb1;

    // prefetch tile 0
    pa0 = *reinterpret_cast<const float4*>(&Ab[(long)(m0 + lr)      * lda + lc]);
    pa1 = *reinterpret_cast<const float4*>(&Ab[(long)(m0 + lr + 64) * lda + lc]);
    pb0 = *reinterpret_cast<const float4*>(&Bb[(long)(n0 + lr)      * ldb + lc]);
    pb1 = *reinterpret_cast<const float4*>(&Bb[(long)(n0 + lr + 64) * ldb + lc]);
    {
        float av0[4] = {pa0.x, pa0.y, pa0.z, pa0.w};
        float av1[4] = {pa1.x, pa1.y, pa1.z, pa1.w};
        float bv0[4] = {pb0.x, pb0.y, pb0.z, pb0.w};
        float bv1[4] = {pb1.x, pb1.y, pb1.z, pb1.w};
#pragma unroll
        for (int i = 0; i < 4; i++) {
            *reinterpret_cast<unsigned long long*>(&As2[0][lc + i][2 * lr])        = pk2(av0[i], av0[i]);
            *reinterpret_cast<unsigned long long*>(&As2[0][lc + i][2 * lr + 128])  = pk2(av1[i], av1[i]);
            Bs[0][lc + i][lr]      = bv0[i];
            Bs[0][lc + i][lr + 64] = bv1[i];
        }
    }
    __syncthreads();

    for (int t = 0; t < nTiles; t++) {
        const int cur = t & 1;
        if (t + 1 < nTiles) {
            const int k0 = (t + 1) * BK;
            pa0 = *reinterpret_cast<const float4*>(&Ab[(long)(m0 + lr)      * lda + k0 + lc]);
            pa1 = *reinterpret_cast<const float4*>(&Ab[(long)(m0 + lr + 64) * lda + k0 + lc]);
            pb0 = *reinterpret_cast<const float4*>(&Bb[(long)(n0 + lr)      * ldb + k0 + lc]);
            pb1 = *reinterpret_cast<const float4*>(&Bb[(long)(n0 + lr + 64) * ldb + k0 + lc]);
        }

#pragma unroll
        for (int k = 0; k < BK; k++) {
            // A dup pairs: rows 4ty..4ty+3 and 64+4ty..+3 (broadcast loads)
            ulonglong2 a01 = *reinterpret_cast<const ulonglong2*>(&As2[cur][k][8 * ty]);
            ulonglong2 a23 = *reinterpret_cast<const ulonglong2*>(&As2[cur][k][8 * ty + 4]);
            ulonglong2 a45 = *reinterpret_cast<const ulonglong2*>(&As2[cur][k][8 * ty + 128]);
            ulonglong2 a67 = *reinterpret_cast<const ulonglong2*>(&As2[cur][k][8 * ty + 132]);
            // B natural pairs: cols {4tx,4tx+1},{4tx+2,4tx+3} and +64
            ulonglong2 b01 = *reinterpret_cast<const ulonglong2*>(&Bs[cur][k][4 * tx]);
            ulonglong2 b23 = *reinterpret_cast<const ulonglong2*>(&Bs[cur][k][4 * tx + 64]);
            unsigned long long ad[8] = {a01.x, a01.y, a23.x, a23.y,
                                        a45.x, a45.y, a67.x, a67.y};
            unsigned long long bp[4] = {b01.x, b01.y, b23.x, b23.y};
#pragma unroll
            for (int r = 0; r < 8; r++)
#pragma unroll
                for (int p = 0; p < 4; p++)
                    ffma2(acc[r][p], ad[r], bp[p]);
        }

        if (t + 1 < nTiles) {
            const int nxt = 1 - cur;
            float av0[4] = {pa0.x, pa0.y, pa0.z, pa0.w};
            float av1[4] = {pa1.x, pa1.y, pa1.z, pa1.w};
            float bv0[4] = {pb0.x, pb0.y, pb0.z, pb0.w};
            float bv1[4] = {pb1.x, pb1.y, pb1.z, pb1.w};
#pragma unroll
            for (int i = 0; i < 4; i++) {
                *reinterpret_cast<unsigned long long*>(&As2[nxt][lc + i][2 * lr])       = pk2(av0[i], av0[i]);
                *reinterpret_cast<unsigned long long*>(&As2[nxt][lc + i][2 * lr + 128]) = pk2(av1[i], av1[i]);
                Bs[nxt][lc + i][lr]      = bv0[i];
                Bs[nxt][lc + i][lr + 64] = bv1[i];
            }
        }
        __syncthreads();
    }

    // epilogue: rows r<4 -> m0+4ty+r; r>=4 -> m0+64+4ty+(r-4)
    //           col-pairs p<2 -> n0+4tx+2p..; p>=2 -> n0+64+4tx+2(p-2)..
    const int cm0 = m0 + ty * 4;
    const int cn0 = n0 + tx * 4;
    float sc[8], sh[8];
    if (bn) {
#pragma unroll
        for (int j = 0; j < 8; j++) {
            int n = (j < 4) ? (cn0 + j) : (cn0 + 60 + j);   // +64 block for j>=4
            float g = bn[n], b = bn[bnN + n], m = bn[2 * bnN + n], v = bn[3 * bnN + n];
            sc[j] = g * rsqrtf(v + EPS);
            sh[j] = b - m * sc[j];
        }
    }
#pragma unroll
    for (int r = 0; r < 8; r++) {
        const int cm = (r < 4) ? (cm0 + r) : (cm0 + 60 + r);
        float c[8];
#pragma unroll
        for (int p = 0; p < 4; p++) upk2(acc[r][p], c[2 * p], c[2 * p + 1]);
        if (bn) {
#pragma unroll
            for (int j = 0; j < 8; j++) {
                float v = c[j] * sc[j] + sh[j];
                c[j] = v > 0.f ? v : 0.2f * v;
            }
        }
        *reinterpret_cast<float4*>(&Cb[(long)cm * ldc + cn0])      = make_float4(c[0], c[1], c[2], c[3]);
        *reinterpret_cast<float4*>(&Cb[(long)cm * ldc + cn0 + 64]) = make_float4(c[4], c[5], c[6], c[7]);
    }
}

// ---------------------------------------------------------------------------
// Gram mirror: fill G[n][m] (m >= 128*((n>>7)+1)) from G[m][n].
// Bit-identical because FMA(a,b,c) == FMA(b,a,c) with same k order.
// ---------------------------------------------------------------------------
__global__ void mirror_kernel(float* __restrict__ G)
{
    int b  = blockIdx.z;
    int m0 = blockIdx.x * 32;   // destination cols
    int n0 = blockIdx.y * 32;   // destination rows
    if (m0 < 128 * ((n0 >> 7) + 1)) return;   // tile already computed

    __shared__ float tile[32][33];
    float* Gb = G + (long)b * NPTS * NPTS;
    int tx = threadIdx.x, ty = threadIdx.y;    // 32 x 8
#pragma unroll
    for (int i = 0; i < 32; i += 8)
        tile[ty + i][tx] = Gb[(long)(m0 + ty + i) * NPTS + n0 + tx];
    __syncthreads();
#pragma unroll
    for (int i = 0; i < 32; i += 8)
        Gb[(long)(n0 + ty + i) * NPTS + m0 + tx] = tile[tx][ty + i];
}

// ---------------------------------------------------------------------------
// Extract Gram diagonal
// ---------------------------------------------------------------------------
__global__ void diag_kernel(const float* __restrict__ G, float* __restrict__ diag)
{
    int t = blockIdx.x * 256 + threadIdx.x;     // over BATCH*NPTS
    int b = t >> 10, m = t & 1023;
    diag[t] = G[((long)b * NPTS + m) * NPTS + m];
}

// ---------------------------------------------------------------------------
// Top-K (K=20): register-resident two-phase selection.
// key[m] = 2*G[n][m] - G[m][m]; descending value, tie -> lower index.
// ---------------------------------------------------------------------------
__global__ void __launch_bounds__(256)
topk_kernel(const float* __restrict__ G, const float* __restrict__ diag,
            int* __restrict__ idx)
{
    const int b = blockIdx.y;
    const int n = blockIdx.x;
    const float* Gb = G + ((long)b * NPTS + n) * NPTS;
    const float* db = diag + b * NPTS;

    const int tid  = threadIdx.x;
    const int lane = tid & 31;
    const int w    = tid >> 5;          // 0..7
    const int base = w * 128;

    float key[4];
#pragma unroll
    for (int q = 0; q < 4; q++) {
        int m = base + lane + 32 * q;
        key[q] = 2.f * Gb[m] - db[m];
    }

    __shared__ float wv[8][KNN];
    __shared__ int   wi[8][KNN];

    // Phase 1: per-warp top-20 (sorted desc, ties by ascending index)
    for (int it = 0; it < KNN; ++it) {
        float bv = key[0];
        int   bi = base + lane;
#pragma unroll
        for (int q = 1; q < 4; q++) {
            if (key[q] > bv) { bv = key[q]; bi = base + lane + 32 * q; }
        }
#pragma unroll
        for (int off = 16; off > 0; off >>= 1) {
            float ov = __shfl_xor_sync(0xffffffffu, bv, off);
            int   oi = __shfl_xor_sync(0xffffffffu, bi, off);
            if (ov > bv || (ov == bv && oi < bi)) { bv = ov; bi = oi; }
        }
        if (lane == 0) { wv[w][it] = bv; wi[w][it] = bi; }
        const int rel   = bi - base;
        const int l_win = rel & 31;
        const int q_win = rel >> 5;
        if (lane == l_win) {
#pragma unroll
            for (int q = 0; q < 4; q++)
                if (q == q_win) key[q] = -CUDART_INF_F;
        }
    }
    __syncthreads();

    // Phase 2: warp 0 merges 8 sorted lists of 20
    if (w == 0) {
        int ptr = 0;
        int* orow = idx + ((long)b * NPTS + n) * KNN;
        for (int it = 0; it < KNN; ++it) {
            float v = (lane < 8) ? wv[lane][ptr] : -CUDART_INF_F;
            int   i = (lane < 8) ? wi[lane][ptr] : 0x7fffffff;
            int   j = lane;
#pragma unroll
            for (int off = 4; off > 0; off >>= 1) {
                float ov = __shfl_xor_sync(0xffffffffu, v, off);
                int   oi = __shfl_xor_sync(0xffffffffu, i, off);
                int   oj = __shfl_xor_sync(0xffffffffu, j, off);
                if (ov > v || (ov == v && oi < i)) { v = ov; i = oi; j = oj; }
            }
            if (lane == 0) orow[it] = i;
            if (lane < 8 && lane == j) ptr++;
        }
    }
}

// ---------------------------------------------------------------------------
// EdgeConv aggregation (float4 across channels):
// out[n][o] = bn_lrelu( max_k U[idx[n,k]][o]  -  U[n][o] + V[n][o] )
// (valid because bn scale > 0 and leaky_relu are monotone increasing)
// ---------------------------------------------------------------------------
__global__ void __launch_bounds__(256)
aggregate_kernel(const float* __restrict__ U, const float* __restrict__ V,
                 const int* __restrict__ idx, const float* __restrict__ bn,
                 float* __restrict__ out, int O, int ldo)
{
    int b = blockIdx.y, n = blockIdx.x;
    __shared__ int nb[KNN];
    int tid = threadIdx.x;
    if (tid < KNN) nb[tid] = idx[((long)b * NPTS + n) * KNN + tid];
    __syncthreads();

    const float* Ub = U + (long)b * NPTS * O;
    const float* un = Ub + (long)n * O;
    const float* vn = V + ((long)b * NPTS + n) * O;
    float*       on = out + ((long)b * NPTS + n) * ldo;

    const int O4 = O >> 2;
    for (int o4 = tid; o4 < O4; o4 += 256) {
        float4 mx = make_float4(-CUDART_INF_F, -CUDART_INF_F, -CUDART_INF_F, -CUDART_INF_F);
#pragma unroll
        for (int k = 0; k < KNN; k++) {
            float4 u = *reinterpret_cast<const float4*>(&Ub[(long)nb[k] * O + o4 * 4]);
            mx.x = fmaxf(mx.x, u.x); mx.y = fmaxf(mx.y, u.y);
            mx.z = fmaxf(mx.z, u.z); mx.w = fmaxf(mx.w, u.w);
        }
        float4 uo = *reinterpret_cast<const float4*>(&un[o4 * 4]);
        float4 vo = *reinterpret_cast<const float4*>(&vn[o4 * 4]);
        float4 gg = *reinterpret_cast<const float4*>(&bn[o4 * 4]);
        float4 be = *reinterpret_cast<const float4*>(&bn[O + o4 * 4]);
        float4 mm = *reinterpret_cast<const float4*>(&bn[2 * O + o4 * 4]);
        float4 vv = *reinterpret_cast<const float4*>(&bn[3 * O + o4 * 4]);
        float y0 = mx.x - uo.x + vo.x, y1 = mx.y - uo.y + vo.y;
        float y2 = mx.z - uo.z + vo.z, y3 = mx.w - uo.w + vo.w;
        float s0 = gg.x * rsqrtf(vv.x + EPS), s1 = gg.y * rsqrtf(vv.y + EPS);
        float s2 = gg.z * rsqrtf(vv.z + EPS), s3 = gg.w * rsqrtf(vv.w + EPS);
        y0 = (y0 - mm.x) * s0 + be.x; y1 = (y1 - mm.y) * s1 + be.y;
        y2 = (y2 - mm.z) * s2 + be.z; y3 = (y3 - mm.w) * s3 + be.w;
        float4 r;
        r.x = y0 > 0.f ? y0 : 0.2f * y0;
        r.y = y1 > 0.f ? y1 : 0.2f * y1;
        r.z = y2 > 0.f ? y2 : 0.2f * y2;
        r.w = y3 > 0.f ? y3 : 0.2f * y3;
        *reinterpret_cast<float4*>(&on[o4 * 4]) = r;
    }
}

// ---------------------------------------------------------------------------
// Pooling (max + mean over N), two-stage
// ---------------------------------------------------------------------------
__global__ void __launch_bounds__(256)
pool1_kernel(const float* __restrict__ H5, float* __restrict__ pmax, float* __restrict__ psum)
{
    int b = blockIdx.y, chunk = blockIdx.x;      // PCH chunks of 32 rows
    int tid = threadIdx.x;
    float mx[4] = {-CUDART_INF_F, -CUDART_INF_F, -CUDART_INF_F, -CUDART_INF_F};
    float sm[4] = {0.f, 0.f, 0.f, 0.f};
    const float* h = H5 + ((long)b * NPTS + chunk * 32) * 1024;
    for (int n = 0; n < 32; n++) {
        const float* row = h + (long)n * 1024;
#pragma unroll
        for (int q = 0; q < 4; q++) {
            float v = row[tid + 256 * q];
            mx[q] = fmaxf(mx[q], v);
            sm[q] += v;
        }
    }
#pragma unroll
    for (int q = 0; q < 4; q++) {
        int o = tid + 256 * q;
        pmax[((long)b * PCH + chunk) * 1024 + o] = mx[q];
        psum[((long)b * PCH + chunk) * 1024 + o] = sm[q];
    }
}

__global__ void __launch_bounds__(256)
pool2_kernel(const float* __restrict__ pmax, const float* __restrict__ psum,
             float* __restrict__ pooled)
{
    int b = blockIdx.y;
    int o = blockIdx.x * 256 + threadIdx.x;      // 0..1023
    float mx = -CUDART_INF_F, sm = 0.f;
    for (int c = 0; c < PCH; c++) {
        mx = fmaxf(mx, pmax[((long)b * PCH + c) * 1024 + o]);
        sm += psum[((long)b * PCH + c) * 1024 + o];
    }
    pooled[b * 2048 + o]        = mx;
    pooled[b * 2048 + 1024 + o] = sm * (1.f / NPTS);
}

// ---------------------------------------------------------------------------
// Head:  z = bn_lrelu(pooled @ Wl1^T);  out = z @ Wl3^T + bl3
// ---------------------------------------------------------------------------
__global__ void __launch_bounds__(256)
head1_kernel(const float* __restrict__ pooled, const float* __restrict__ Wl1,
             const float* __restrict__ bn6, float* __restrict__ z)
{
    int b = blockIdx.y, j = blockIdx.x;          // j < 512
    int tid = threadIdx.x;
    const float* p = pooled + b * 2048;
    const float* w = Wl1 + (long)j * 2048;
    float s = 0.f;
    for (int c = tid; c < 2048; c += 256) s += p[c] * w[c];
    __shared__ float red[256];
    red[tid] = s; __syncthreads();
    for (int st = 128; st > 0; st >>= 1) {
        if (tid < st) red[tid] += red[tid + st];
        __syncthreads();
    }
    if (tid == 0) {
        float y = red[0];
        float g = bn6[j], be = bn6[512 + j], mm = bn6[1024 + j], vv = bn6[1536 + j];
        y = (y - mm) * (g * rsqrtf(vv + EPS)) + be;
        z[b * 512 + j] = y > 0.f ? y : 0.2f * y;
    }
}

__global__ void __launch_bounds__(128)
head2_kernel(const float* __restrict__ z, const float* __restrict__ Wl3,
             const float* __restrict__ bl3, float* __restrict__ out)
{
    int b = blockIdx.y, t = blockIdx.x;          // t < 40
    int tid = threadIdx.x;
    const float* zb = z + b * 512;
    const float* w  = Wl3 + (long)t * 512;
    float s = 0.f;
    for (int c = tid; c < 512; c += 128) s += zb[c] * w[c];
    __shared__ float red[128];
    red[tid] = s; __syncthreads();
    for (int st = 64; st > 0; st >>= 1) {
        if (tid < st) red[tid] += red[tid + st];
        __syncthreads();
    }
    if (tid == 0) out[b * 40 + t] = red[0] + bl3[t];
}

// ---------------------------------------------------------------------------
// Host driver
// ---------------------------------------------------------------------------
static void launch_gemm2(const float* A, int lda, long sA,
                         const float* B1, const float* B2, int ldb, long sB,
                         float* C1, float* C2, int ldc, long sC,
                         int M, int N1, int N2, int K,
                         const float* bn, int bnN, int sym)
{
    dim3 grid((N1 + N2) / BN, M / BM, BATCH);
    gemm_nt<<<grid, 256>>>(A, lda, sA, B1, B2, ldb, sB, C1, C2, ldc, sC, N1, K, bn, bnN, sym);
}

static void run_edgeconv(const float* Xin, int lda, int Kdim,
                         const float* W, const float* bn, int O,
                         float* Hout, int ldo,
                         float* G, float* diag, int* idx, float* U, float* V)
{
    // 1) Gram matrix (lower-triangular block region), mirror
    launch_gemm2(Xin, lda, (long)NPTS * lda, Xin, Xin, lda, (long)NPTS * lda,
                 G, G, NPTS, (long)NPTS * NPTS, NPTS, NPTS, 0, Kdim, nullptr, 0, 1);
    mirror_kernel<<<dim3(NPTS / 32, NPTS / 32, BATCH), dim3(32, 8)>>>(G);
    // 2) fused U/V gemm (4th launch overall for conv1 -> profiled)
    launch_gemm2(Xin, lda, (long)NPTS * lda, W, W + Kdim, 2 * Kdim, 0,
                 U, V, O, (long)NPTS * O, NPTS, O, O, Kdim, nullptr, 0, 0);
    // 3) diag + top-20 per row
    diag_kernel<<<(BATCH * NPTS) / 256, 256>>>(G, diag);
    topk_kernel<<<dim3(NPTS, BATCH), 256>>>(G, diag, idx);
    // 4) gather + max + bn + lrelu
    aggregate_kernel<<<dim3(NPTS, BATCH), 256>>>(U, V, idx, bn, Hout, O, ldo);
}

extern "C" void kernel_launch(void* const* d_in, const int* in_sizes, int n_in,
                              void* d_out, int out_size)
{
    (void)in_sizes; (void)n_in; (void)out_size;
    const float* x   = (const float*)d_in[0];
    const float* W1  = (const float*)d_in[1];
    const float* bn1 = (const float*)d_in[2];
    const float* W2  = (const float*)d_in[3];
    const float* bn2 = (const float*)d_in[4];
    const float* W3  = (const float*)d_in[5];
    const float* bn3 = (const float*)d_in[6];
    const float* W4  = (const float*)d_in[7];
    const float* bn4 = (const float*)d_in[8];
    const float* W5  = (const float*)d_in[9];
    const float* bn5 = (const float*)d_in[10];
    const float* Wl1 = (const float*)d_in[11];
    const float* bn6 = (const float*)d_in[12];
    const float* Wl3 = (const float*)d_in[13];
    const float* bl3 = (const float*)d_in[14];
    float* out = (float*)d_out;

    float *XT, *G, *diag, *U, *V, *H, *H5, *pmax, *psum, *pool, *z;
    int* idx;
    cudaGetSymbolAddress((void**)&XT,   g_XT);
    cudaGetSymbolAddress((void**)&G,    g_G);
    cudaGetSymbolAddress((void**)&diag, g_diag);
    cudaGetSymbolAddress((void**)&idx,  g_idx);
    cudaGetSymbolAddress((void**)&U,    g_U);
    cudaGetSymbolAddress((void**)&V,    g_V);
    cudaGetSymbolAddress((void**)&H,    g_H);
    cudaGetSymbolAddress((void**)&H5,   g_H5);
    cudaGetSymbolAddress((void**)&pmax, g_pmax);
    cudaGetSymbolAddress((void**)&psum, g_psum);
    cudaGetSymbolAddress((void**)&pool, g_pool);
    cudaGetSymbolAddress((void**)&z,    g_z);

    // transpose x (B,C,N) -> XT (B,N,C)
    transpose_kernel<<<dim3(NPTS / 32, CIN / 32, BATCH), dim3(32, 8)>>>(x, XT);

    // EdgeConv 1..4, outputs written into slices of H (ld = 1152)
    run_edgeconv(XT,      CIN,  768, W1, bn1, 512, H,       HDIM, G, diag, idx, U, V);
    run_edgeconv(H,       HDIM, 512, W2, bn2, 256, H + 512, HDIM, G, diag, idx, U, V);
    run_edgeconv(H + 512, HDIM, 256, W3, bn3, 128, H + 768, HDIM, G, diag, idx, U, V);
    run_edgeconv(H + 768, HDIM, 128, W4, bn4, 256, H + 896, HDIM, G, diag, idx, U, V);

    // conv5: H (N x 1152) @ W5^T (1152 x 1024) + bn5 + lrelu  -> H5
    launch_gemm2(H, HDIM, (long)NPTS * HDIM, W5, W5, HDIM, 0,
                 H5, H5, 1024, (long)NPTS * 1024, NPTS, 1024, 0, HDIM, bn5, 1024, 0);

    // pooling -> pooled (B x 2048)
    pool1_kernel<<<dim3(PCH, BATCH), 256>>>(H5, pmax, psum);
    pool2_kernel<<<dim3(4, BATCH), 256>>>(pmax, psum, pool);

    // head
    head1_kernel<<<dim3(512, BATCH), 256>>>(pool, Wl1, bn6, z);
    head2_kernel<<<dim3(40, BATCH), 128>>>(z, Wl3, bl3, out);
}

// round 11
// speedup vs baseline: 1.2007x; 1.2007x over previous
#include <cuda_runtime.h>
#include <math_constants.h>

// ---------------------------------------------------------------------------
// Problem constants
// ---------------------------------------------------------------------------
#define BATCH 4
#define NPTS  1024
#define CIN   768
#define KNN   20
#define HDIM  1152    // 512 + 256 + 128 + 256
#define PCH   32      // pooling chunks
#define EPS   1e-5f

// ---------------------------------------------------------------------------
// Scratch (device globals; no allocation allowed)
// ---------------------------------------------------------------------------
__device__ float g_XT [BATCH * NPTS * CIN];     // x transposed: (B, N, C)
__device__ float g_G  [BATCH * NPTS * NPTS];    // gram matrix
__device__ float g_diag[BATCH * NPTS];          // gram diagonal
__device__ int   g_idx[BATCH * NPTS * KNN];     // knn indices
__device__ float g_U  [BATCH * NPTS * 512];     // W_left  @ x
__device__ float g_V  [BATCH * NPTS * 512];     // W_right @ x
__device__ float g_H  [BATCH * NPTS * HDIM];    // concat(x1,x2,x3,x4)
__device__ float g_H5 [BATCH * NPTS * 1024];    // conv5 output
__device__ float g_pmax[BATCH * PCH * 1024];
__device__ float g_psum[BATCH * PCH * 1024];
__device__ float g_pool[BATCH * 2048];
__device__ float g_z   [BATCH * 512];

// ---------------------------------------------------------------------------
// Transpose: x (B, C, N) -> XT (B, N, C)
// ---------------------------------------------------------------------------
__global__ void transpose_kernel(const float* __restrict__ x, float* __restrict__ xt) {
    __shared__ float tile[32][33];
    int b  = blockIdx.z;
    int c0 = blockIdx.y * 32;
    int n0 = blockIdx.x * 32;
    const float* xb  = x  + (long)b * CIN * NPTS;
    float*       xtb = xt + (long)b * NPTS * CIN;
    int tx = threadIdx.x, ty = threadIdx.y;            // 32 x 8
#pragma unroll
    for (int i = 0; i < 32; i += 8)
        tile[ty + i][tx] = xb[(long)(c0 + ty + i) * NPTS + n0 + tx];
    __syncthreads();
#pragma unroll
    for (int i = 0; i < 32; i += 8)
        xtb[(long)(n0 + ty + i) * CIN + c0 + tx] = tile[tx][ty + i];
}

// ---------------------------------------------------------------------------
// Tiled SGEMM with dual-source N split (measured 34.4 TF/s config):
//   blocks with nb0 <  N1 compute C1 = A * B1^T
//   blocks with nb0 >= N1 compute C2 = A * B2^T  (column nb0-N1)
// 128x64 tiles, 8x4 per-thread register blocking, double-buffered smem,
// 256 threads, 3 CTAs/SM. Conflict-free smem loads (B at 16B stride).
// Sequential k accumulation -> bit-identical numerics across rounds.
// sym != 0: only blocks with bx <= 2*by+1 computed (Gram symmetry;
//           exactly covers the region mirror_kernel expects).
// Optional epilogue: batchnorm + leaky_relu(0.2).
// Requirements: M % 128 == 0, N % 64 == 0, K % 16 == 0
// ---------------------------------------------------------------------------
#define BM 128
#define BN 64
#define BK 16

__global__ void __launch_bounds__(256, 3)
gemm_nt(const float* __restrict__ A, int lda, long strideA,
        const float* __restrict__ B1, const float* __restrict__ B2,
        int ldb, long strideB,
        float* __restrict__ C1, float* __restrict__ C2,
        int ldc, long strideC,
        int N1, int K,
        const float* __restrict__ bn, int bnN, int sym)
{
    if (sym && (int)blockIdx.x > 2 * (int)blockIdx.y + 1) return;

    __shared__ __align__(16) float As[2][BK][BM];
    __shared__ __align__(16) float Bs[2][BK][BN];

    const int bz = blockIdx.z;
    const int m0 = blockIdx.y * BM;
    const int nb0 = blockIdx.x * BN;

    const float* Bsel;
    float*       Csel;
    int n0;
    if (nb0 < N1) { Bsel = B1; Csel = C1; n0 = nb0; }
    else          { Bsel = B2; Csel = C2; n0 = nb0 - N1; }

    const float* Ab = A    + (long)bz * strideA;
    const float* Bb = Bsel + (long)bz * strideB;
    float*       Cb = Csel + (long)bz * strideC;

    const int tid = threadIdx.x;
    // loader mapping
    const int lr = tid >> 2;            // 0..63
    const int lc = (tid & 3) * 4;       // 0,4,8,12
    // compute mapping: 16x16 thread grid; each thread 8 rows x 4 cols
    const int ty = tid >> 4;            // 0..15
    const int tx = tid & 15;            // 0..15

    float acc[8][4];
#pragma unroll
    for (int i = 0; i < 8; i++)
#pragma unroll
        for (int j = 0; j < 4; j++) acc[i][j] = 0.f;

    const int nTiles = K / BK;
    float4 pa0, pa1, pb0;

    // prefetch tile 0
    pa0 = *reinterpret_cast<const float4*>(&Ab[(long)(m0 + lr)      * lda + lc]);
    pa1 = *reinterpret_cast<const float4*>(&Ab[(long)(m0 + lr + 64) * lda + lc]);
    pb0 = *reinterpret_cast<const float4*>(&Bb[(long)(n0 + lr)      * ldb + lc]);
    As[0][lc + 0][lr] = pa0.x; As[0][lc + 1][lr] = pa0.y;
    As[0][lc + 2][lr] = pa0.z; As[0][lc + 3][lr] = pa0.w;
    As[0][lc + 0][lr + 64] = pa1.x; As[0][lc + 1][lr + 64] = pa1.y;
    As[0][lc + 2][lr + 64] = pa1.z; As[0][lc + 3][lr + 64] = pa1.w;
    Bs[0][lc + 0][lr] = pb0.x; Bs[0][lc + 1][lr] = pb0.y;
    Bs[0][lc + 2][lr] = pb0.z; Bs[0][lc + 3][lr] = pb0.w;
    __syncthreads();

    for (int t = 0; t < nTiles; t++) {
        const int cur = t & 1;
        if (t + 1 < nTiles) {
            const int k0 = (t + 1) * BK;
            pa0 = *reinterpret_cast<const float4*>(&Ab[(long)(m0 + lr)      * lda + k0 + lc]);
            pa1 = *reinterpret_cast<const float4*>(&Ab[(long)(m0 + lr + 64) * lda + k0 + lc]);
            pb0 = *reinterpret_cast<const float4*>(&Bb[(long)(n0 + lr)      * ldb + k0 + lc]);
        }

#pragma unroll
        for (int k = 0; k < BK; k++) {
            float4 a0 = *reinterpret_cast<const float4*>(&As[cur][k][ty * 8]);
            float4 a1 = *reinterpret_cast<const float4*>(&As[cur][k][ty * 8 + 4]);
            float4 b0 = *reinterpret_cast<const float4*>(&Bs[cur][k][tx * 4]);
            float av[8] = {a0.x, a0.y, a0.z, a0.w, a1.x, a1.y, a1.z, a1.w};
            float bv[4] = {b0.x, b0.y, b0.z, b0.w};
#pragma unroll
            for (int i = 0; i < 8; i++)
#pragma unroll
                for (int j = 0; j < 4; j++)
                    acc[i][j] += av[i] * bv[j];
        }

        if (t + 1 < nTiles) {
            const int nxt = 1 - cur;
            As[nxt][lc + 0][lr] = pa0.x; As[nxt][lc + 1][lr] = pa0.y;
            As[nxt][lc + 2][lr] = pa0.z; As[nxt][lc + 3][lr] = pa0.w;
            As[nxt][lc + 0][lr + 64] = pa1.x; As[nxt][lc + 1][lr + 64] = pa1.y;
            As[nxt][lc + 2][lr + 64] = pa1.z; As[nxt][lc + 3][lr + 64] = pa1.w;
            Bs[nxt][lc + 0][lr] = pb0.x; Bs[nxt][lc + 1][lr] = pb0.y;
            Bs[nxt][lc + 2][lr] = pb0.z; Bs[nxt][lc + 3][lr] = pb0.w;
        }
        __syncthreads();
    }

    // epilogue
    const int cm = m0 + ty * 8;
    const int cn = n0 + tx * 4;
    if (bn) {
        float sc[4], sh[4];
#pragma unroll
        for (int j = 0; j < 4; j++) {
            int n = cn + j;
            float g = bn[n], b = bn[bnN + n], m = bn[2 * bnN + n], v = bn[3 * bnN + n];
            sc[j] = g * rsqrtf(v + EPS);
            sh[j] = b - m * sc[j];
        }
#pragma unroll
        for (int i = 0; i < 8; i++) {
#pragma unroll
            for (int j = 0; j < 4; j++) {
                float val = acc[i][j] * sc[j] + sh[j];
                acc[i][j] = val > 0.f ? val : 0.2f * val;
            }
        }
    }
#pragma unroll
    for (int i = 0; i < 8; i++) {
        float4 v0 = make_float4(acc[i][0], acc[i][1], acc[i][2], acc[i][3]);
        *reinterpret_cast<float4*>(&Cb[(long)(cm + i) * ldc + cn]) = v0;
    }
}

// ---------------------------------------------------------------------------
// Gram mirror: fill G[n][m] (m >= 128*((n>>7)+1)) from G[m][n].
// Bit-identical because FMA(a,b,c) == FMA(b,a,c) with same k order.
// ---------------------------------------------------------------------------
__global__ void mirror_kernel(float* __restrict__ G)
{
    int b  = blockIdx.z;
    int m0 = blockIdx.x * 32;   // destination cols
    int n0 = blockIdx.y * 32;   // destination rows
    if (m0 < 128 * ((n0 >> 7) + 1)) return;   // tile already computed

    __shared__ float tile[32][33];
    float* Gb = G + (long)b * NPTS * NPTS;
    int tx = threadIdx.x, ty = threadIdx.y;    // 32 x 8
#pragma unroll
    for (int i = 0; i < 32; i += 8)
        tile[ty + i][tx] = Gb[(long)(m0 + ty + i) * NPTS + n0 + tx];
    __syncthreads();
#pragma unroll
    for (int i = 0; i < 32; i += 8)
        Gb[(long)(n0 + ty + i) * NPTS + m0 + tx] = tile[tx][ty + i];
}

// ---------------------------------------------------------------------------
// Extract Gram diagonal
// ---------------------------------------------------------------------------
__global__ void diag_kernel(const float* __restrict__ G, float* __restrict__ diag)
{
    int t = blockIdx.x * 256 + threadIdx.x;     // over BATCH*NPTS
    int b = t >> 10, m = t & 1023;
    diag[t] = G[((long)b * NPTS + m) * NPTS + m];
}

// ---------------------------------------------------------------------------
// Top-K (K=20): register-resident two-phase selection.
// key[m] = 2*G[n][m] - G[m][m]; descending value, tie -> lower index.
// ---------------------------------------------------------------------------
__global__ void __launch_bounds__(256)
topk_kernel(const float* __restrict__ G, const float* __restrict__ diag,
            int* __restrict__ idx)
{
    const int b = blockIdx.y;
    const int n = blockIdx.x;
    const float* Gb = G + ((long)b * NPTS + n) * NPTS;
    const float* db = diag + b * NPTS;

    const int tid  = threadIdx.x;
    const int lane = tid & 31;
    const int w    = tid >> 5;          // 0..7
    const int base = w * 128;

    float key[4];
#pragma unroll
    for (int q = 0; q < 4; q++) {
        int m = base + lane + 32 * q;
        key[q] = 2.f * Gb[m] - db[m];
    }

    __shared__ float wv[8][KNN];
    __shared__ int   wi[8][KNN];

    // Phase 1: per-warp top-20 (sorted desc, ties by ascending index)
    for (int it = 0; it < KNN; ++it) {
        float bv = key[0];
        int   bi = base + lane;
#pragma unroll
        for (int q = 1; q < 4; q++) {
            if (key[q] > bv) { bv = key[q]; bi = base + lane + 32 * q; }
        }
#pragma unroll
        for (int off = 16; off > 0; off >>= 1) {
            float ov = __shfl_xor_sync(0xffffffffu, bv, off);
            int   oi = __shfl_xor_sync(0xffffffffu, bi, off);
            if (ov > bv || (ov == bv && oi < bi)) { bv = ov; bi = oi; }
        }
        if (lane == 0) { wv[w][it] = bv; wi[w][it] = bi; }
        const int rel   = bi - base;
        const int l_win = rel & 31;
        const int q_win = rel >> 5;
        if (lane == l_win) {
#pragma unroll
            for (int q = 0; q < 4; q++)
                if (q == q_win) key[q] = -CUDART_INF_F;
        }
    }
    __syncthreads();

    // Phase 2: warp 0 merges 8 sorted lists of 20
    if (w == 0) {
        int ptr = 0;
        int* orow = idx + ((long)b * NPTS + n) * KNN;
        for (int it = 0; it < KNN; ++it) {
            float v = (lane < 8) ? wv[lane][ptr] : -CUDART_INF_F;
            int   i = (lane < 8) ? wi[lane][ptr] : 0x7fffffff;
            int   j = lane;
#pragma unroll
            for (int off = 4; off > 0; off >>= 1) {
                float ov = __shfl_xor_sync(0xffffffffu, v, off);
                int   oi = __shfl_xor_sync(0xffffffffu, i, off);
                int   oj = __shfl_xor_sync(0xffffffffu, j, off);
                if (ov > v || (ov == v && oi < i)) { v = ov; i = oi; j = oj; }
            }
            if (lane == 0) orow[it] = i;
            if (lane < 8 && lane == j) ptr++;
        }
    }
}

// ---------------------------------------------------------------------------
// EdgeConv aggregation (float4 across channels):
// out[n][o] = bn_lrelu( max_k U[idx[n,k]][o]  -  U[n][o] + V[n][o] )
// (valid because bn scale > 0 and leaky_relu are monotone increasing)
// ---------------------------------------------------------------------------
__global__ void __launch_bounds__(256)
aggregate_kernel(const float* __restrict__ U, const float* __restrict__ V,
                 const int* __restrict__ idx, const float* __restrict__ bn,
                 float* __restrict__ out, int O, int ldo)
{
    int b = blockIdx.y, n = blockIdx.x;
    __shared__ int nb[KNN];
    int tid = threadIdx.x;
    if (tid < KNN) nb[tid] = idx[((long)b * NPTS + n) * KNN + tid];
    __syncthreads();

    const float* Ub = U + (long)b * NPTS * O;
    const float* un = Ub + (long)n * O;
    const float* vn = V + ((long)b * NPTS + n) * O;
    float*       on = out + ((long)b * NPTS + n) * ldo;

    const int O4 = O >> 2;
    for (int o4 = tid; o4 < O4; o4 += 256) {
        float4 mx = make_float4(-CUDART_INF_F, -CUDART_INF_F, -CUDART_INF_F, -CUDART_INF_F);
#pragma unroll
        for (int k = 0; k < KNN; k++) {
            float4 u = *reinterpret_cast<const float4*>(&Ub[(long)nb[k] * O + o4 * 4]);
            mx.x = fmaxf(mx.x, u.x); mx.y = fmaxf(mx.y, u.y);
            mx.z = fmaxf(mx.z, u.z); mx.w = fmaxf(mx.w, u.w);
        }
        float4 uo = *reinterpret_cast<const float4*>(&un[o4 * 4]);
        float4 vo = *reinterpret_cast<const float4*>(&vn[o4 * 4]);
        float4 gg = *reinterpret_cast<const float4*>(&bn[o4 * 4]);
        float4 be = *reinterpret_cast<const float4*>(&bn[O + o4 * 4]);
        float4 mm = *reinterpret_cast<const float4*>(&bn[2 * O + o4 * 4]);
        float4 vv = *reinterpret_cast<const float4*>(&bn[3 * O + o4 * 4]);
        float y0 = mx.x - uo.x + vo.x, y1 = mx.y - uo.y + vo.y;
        float y2 = mx.z - uo.z + vo.z, y3 = mx.w - uo.w + vo.w;
        float s0 = gg.x * rsqrtf(vv.x + EPS), s1 = gg.y * rsqrtf(vv.y + EPS);
        float s2 = gg.z * rsqrtf(vv.z + EPS), s3 = gg.w * rsqrtf(vv.w + EPS);
        y0 = (y0 - mm.x) * s0 + be.x; y1 = (y1 - mm.y) * s1 + be.y;
        y2 = (y2 - mm.z) * s2 + be.z; y3 = (y3 - mm.w) * s3 + be.w;
        float4 r;
        r.x = y0 > 0.f ? y0 : 0.2f * y0;
        r.y = y1 > 0.f ? y1 : 0.2f * y1;
        r.z = y2 > 0.f ? y2 : 0.2f * y2;
        r.w = y3 > 0.f ? y3 : 0.2f * y3;
        *reinterpret_cast<float4*>(&on[o4 * 4]) = r;
    }
}

// ---------------------------------------------------------------------------
// Pooling (max + mean over N), two-stage
// ---------------------------------------------------------------------------
__global__ void __launch_bounds__(256)
pool1_kernel(const float* __restrict__ H5, float* __restrict__ pmax, float* __restrict__ psum)
{
    int b = blockIdx.y, chunk = blockIdx.x;      // PCH chunks of 32 rows
    int tid = threadIdx.x;
    float mx[4] = {-CUDART_INF_F, -CUDART_INF_F, -CUDART_INF_F, -CUDART_INF_F};
    float sm[4] = {0.f, 0.f, 0.f, 0.f};
    const float* h = H5 + ((long)b * NPTS + chunk * 32) * 1024;
    for (int n = 0; n < 32; n++) {
        const float* row = h + (long)n * 1024;
#pragma unroll
        for (int q = 0; q < 4; q++) {
            float v = row[tid + 256 * q];
            mx[q] = fmaxf(mx[q], v);
            sm[q] += v;
        }
    }
#pragma unroll
    for (int q = 0; q < 4; q++) {
        int o = tid + 256 * q;
        pmax[((long)b * PCH + chunk) * 1024 + o] = mx[q];
        psum[((long)b * PCH + chunk) * 1024 + o] = sm[q];
    }
}

__global__ void __launch_bounds__(256)
pool2_kernel(const float* __restrict__ pmax, const float* __restrict__ psum,
             float* __restrict__ pooled)
{
    int b = blockIdx.y;
    int o = blockIdx.x * 256 + threadIdx.x;      // 0..1023
    float mx = -CUDART_INF_F, sm = 0.f;
    for (int c = 0; c < PCH; c++) {
        mx = fmaxf(mx, pmax[((long)b * PCH + c) * 1024 + o]);
        sm += psum[((long)b * PCH + c) * 1024 + o];
    }
    pooled[b * 2048 + o]        = mx;
    pooled[b * 2048 + 1024 + o] = sm * (1.f / NPTS);
}

// ---------------------------------------------------------------------------
// Head:  z = bn_lrelu(pooled @ Wl1^T);  out = z @ Wl3^T + bl3
// ---------------------------------------------------------------------------
__global__ void __launch_bounds__(256)
head1_kernel(const float* __restrict__ pooled, const float* __restrict__ Wl1,
             const float* __restrict__ bn6, float* __restrict__ z)
{
    int b = blockIdx.y, j = blockIdx.x;          // j < 512
    int tid = threadIdx.x;
    const float* p = pooled + b * 2048;
    const float* w = Wl1 + (long)j * 2048;
    float s = 0.f;
    for (int c = tid; c < 2048; c += 256) s += p[c] * w[c];
    __shared__ float red[256];
    red[tid] = s; __syncthreads();
    for (int st = 128; st > 0; st >>= 1) {
        if (tid < st) red[tid] += red[tid + st];
        __syncthreads();
    }
    if (tid == 0) {
        float y = red[0];
        float g = bn6[j], be = bn6[512 + j], mm = bn6[1024 + j], vv = bn6[1536 + j];
        y = (y - mm) * (g * rsqrtf(vv + EPS)) + be;
        z[b * 512 + j] = y > 0.f ? y : 0.2f * y;
    }
}

__global__ void __launch_bounds__(128)
head2_kernel(const float* __restrict__ z, const float* __restrict__ Wl3,
             const float* __restrict__ bl3, float* __restrict__ out)
{
    int b = blockIdx.y, t = blockIdx.x;          // t < 40
    int tid = threadIdx.x;
    const float* zb = z + b * 512;
    const float* w  = Wl3 + (long)t * 512;
    float s = 0.f;
    for (int c = tid; c < 512; c += 128) s += zb[c] * w[c];
    __shared__ float red[128];
    red[tid] = s; __syncthreads();
    for (int st = 64; st > 0; st >>= 1) {
        if (tid < st) red[tid] += red[tid + st];
        __syncthreads();
    }
    if (tid == 0) out[b * 40 + t] = red[0] + bl3[t];
}

// ---------------------------------------------------------------------------
// Host driver. A side stream runs the U/V GEMM concurrently with the
// gram -> mirror -> diag -> topk chain (they share only the input x_i).
// Stream/events are created once on the first (correctness, pre-capture)
// call; the fork/join event pattern is the standard capturable idiom.
// ---------------------------------------------------------------------------
static cudaStream_t s_side = nullptr;
static cudaEvent_t  s_fork[4], s_join[4];

static void ensure_side_stream()
{
    if (!s_side) {
        cudaStreamCreateWithFlags(&s_side, cudaStreamNonBlocking);
        for (int i = 0; i < 4; i++) {
            cudaEventCreateWithFlags(&s_fork[i], cudaEventDisableTiming);
            cudaEventCreateWithFlags(&s_join[i], cudaEventDisableTiming);
        }
    }
}

static void launch_gemm2(cudaStream_t st,
                         const float* A, int lda, long sA,
                         const float* B1, const float* B2, int ldb, long sB,
                         float* C1, float* C2, int ldc, long sC,
                         int M, int N1, int N2, int K,
                         const float* bn, int bnN, int sym)
{
    dim3 grid((N1 + N2) / BN, M / BM, BATCH);
    gemm_nt<<<grid, 256, 0, st>>>(A, lda, sA, B1, B2, ldb, sB, C1, C2, ldc, sC,
                                  N1, K, bn, bnN, sym);
}

static void run_edgeconv(int ci, const float* Xin, int lda, int Kdim,
                         const float* W, const float* bn, int O,
                         float* Hout, int ldo,
                         float* G, float* diag, int* idx, float* U, float* V)
{
    // fork: U/V gemm on the side stream (depends only on Xin)
    cudaEventRecord(s_fork[ci], 0);
    cudaStreamWaitEvent(s_side, s_fork[ci], 0);
    launch_gemm2(s_side, Xin, lda, (long)NPTS * lda, W, W + Kdim, 2 * Kdim, 0,
                 U, V, O, (long)NPTS * O, NPTS, O, O, Kdim, nullptr, 0, 0);
    cudaEventRecord(s_join[ci], s_side);

    // main stream: gram (lower-triangular block region) -> mirror -> diag -> topk
    launch_gemm2(0, Xin, lda, (long)NPTS * lda, Xin, Xin, lda, (long)NPTS * lda,
                 G, G, NPTS, (long)NPTS * NPTS, NPTS, NPTS, 0, Kdim, nullptr, 0, 1);
    mirror_kernel<<<dim3(NPTS / 32, NPTS / 32, BATCH), dim3(32, 8)>>>(G);
    diag_kernel<<<(BATCH * NPTS) / 256, 256>>>(G, diag);
    topk_kernel<<<dim3(NPTS, BATCH), 256>>>(G, diag, idx);

    // join: aggregation needs both topk (main) and U/V (side)
    cudaStreamWaitEvent(0, s_join[ci], 0);
    aggregate_kernel<<<dim3(NPTS, BATCH), 256>>>(U, V, idx, bn, Hout, O, ldo);
}

extern "C" void kernel_launch(void* const* d_in, const int* in_sizes, int n_in,
                              void* d_out, int out_size)
{
    (void)in_sizes; (void)n_in; (void)out_size;
    const float* x   = (const float*)d_in[0];
    const float* W1  = (const float*)d_in[1];
    const float* bn1 = (const float*)d_in[2];
    const float* W2  = (const float*)d_in[3];
    const float* bn2 = (const float*)d_in[4];
    const float* W3  = (const float*)d_in[5];
    const float* bn3 = (const float*)d_in[6];
    const float* W4  = (const float*)d_in[7];
    const float* bn4 = (const float*)d_in[8];
    const float* W5  = (const float*)d_in[9];
    const float* bn5 = (const float*)d_in[10];
    const float* Wl1 = (const float*)d_in[11];
    const float* bn6 = (const float*)d_in[12];
    const float* Wl3 = (const float*)d_in[13];
    const float* bl3 = (const float*)d_in[14];
    float* out = (float*)d_out;

    ensure_side_stream();

    float *XT, *G, *diag, *U, *V, *H, *H5, *pmax, *psum, *pool, *z;
    int* idx;
    cudaGetSymbolAddress((void**)&XT,   g_XT);
    cudaGetSymbolAddress((void**)&G,    g_G);
    cudaGetSymbolAddress((void**)&diag, g_diag);
    cudaGetSymbolAddress((void**)&idx,  g_idx);
    cudaGetSymbolAddress((void**)&U,    g_U);
    cudaGetSymbolAddress((void**)&V,    g_V);
    cudaGetSymbolAddress((void**)&H,    g_H);
    cudaGetSymbolAddress((void**)&H5,   g_H5);
    cudaGetSymbolAddress((void**)&pmax, g_pmax);
    cudaGetSymbolAddress((void**)&psum, g_psum);
    cudaGetSymbolAddress((void**)&pool, g_pool);
    cudaGetSymbolAddress((void**)&z,    g_z);

    // transpose x (B,C,N) -> XT (B,N,C)
    transpose_kernel<<<dim3(NPTS / 32, CIN / 32, BATCH), dim3(32, 8)>>>(x, XT);

    // EdgeConv 1..4, outputs written into slices of H (ld = 1152)
    run_edgeconv(0, XT,      CIN,  768, W1, bn1, 512, H,       HDIM, G, diag, idx, U, V);
    run_edgeconv(1, H,       HDIM, 512, W2, bn2, 256, H + 512, HDIM, G, diag, idx, U, V);
    run_edgeconv(2, H + 512, HDIM, 256, W3, bn3, 128, H + 768, HDIM, G, diag, idx, U, V);
    run_edgeconv(3, H + 768, HDIM, 128, W4, bn4, 256, H + 896, HDIM, G, diag, idx, U, V);

    // conv5: H (N x 1152) @ W5^T (1152 x 1024) + bn5 + lrelu  -> H5
    launch_gemm2(0, H, HDIM, (long)NPTS * HDIM, W5, W5, HDIM, 0,
                 H5, H5, 1024, (long)NPTS * 1024, NPTS, 1024, 0, HDIM, bn5, 1024, 0);

    // pooling -> pooled (B x 2048)
    pool1_kernel<<<dim3(PCH, BATCH), 256>>>(H5, pmax, psum);
    pool2_kernel<<<dim3(4, BATCH), 256>>>(pmax, psum, pool);

    // head
    head1_kernel<<<dim3(512, BATCH), 256>>>(pool, Wl1, bn6, z);
    head2_kernel<<<dim3(40, BATCH), 128>>>(z, Wl3, bl3, out);
}

// round 14
// speedup vs baseline: 1.2684x; 1.0564x over previous
#include <cuda_runtime.h>
#include <math_constants.h>

// ---------------------------------------------------------------------------
// Problem constants
// ---------------------------------------------------------------------------
#define BATCH 4
#define NPTS  1024
#define CIN   768
#define KNN   20
#define HDIM  1152    // 512 + 256 + 128 + 256
#define PCH   32      // pooling chunks
#define EPS   1e-5f

// ---------------------------------------------------------------------------
// Scratch (device globals; no allocation allowed)
// ---------------------------------------------------------------------------
__device__ float g_XT [BATCH * NPTS * CIN];     // x transposed: (B, N, C)
__device__ float g_G  [BATCH * NPTS * NPTS];    // gram matrix
__device__ float g_diag[BATCH * NPTS];          // gram diagonal
__device__ int   g_idx[BATCH * NPTS * KNN];     // knn indices
__device__ float g_U  [BATCH * NPTS * 512];     // W_left  @ x
__device__ float g_V  [BATCH * NPTS * 512];     // W_right @ x
__device__ float g_H  [BATCH * NPTS * HDIM];    // concat(x1,x2,x3,x4)
__device__ float g_H5 [BATCH * NPTS * 1024];    // conv5 output
__device__ float g_pmax[BATCH * PCH * 1024];
__device__ float g_psum[BATCH * PCH * 1024];
__device__ float g_pool[BATCH * 2048];
__device__ float g_z   [BATCH * 512];

// ---------------------------------------------------------------------------
// Transpose: x (B, C, N) -> XT (B, N, C)
// ---------------------------------------------------------------------------
__global__ void transpose_kernel(const float* __restrict__ x, float* __restrict__ xt) {
    __shared__ float tile[32][33];
    int b  = blockIdx.z;
    int c0 = blockIdx.y * 32;
    int n0 = blockIdx.x * 32;
    const float* xb  = x  + (long)b * CIN * NPTS;
    float*       xtb = xt + (long)b * NPTS * CIN;
    int tx = threadIdx.x, ty = threadIdx.y;            // 32 x 8
#pragma unroll
    for (int i = 0; i < 32; i += 8)
        tile[ty + i][tx] = xb[(long)(c0 + ty + i) * NPTS + n0 + tx];
    __syncthreads();
#pragma unroll
    for (int i = 0; i < 32; i += 8)
        xtb[(long)(n0 + ty + i) * CIN + c0 + tx] = tile[tx][ty + i];
}

// ---------------------------------------------------------------------------
// Tiled SGEMM with dual-source N split (measured 34.4 TF/s config):
//   blocks with nb0 <  N1 compute C1 = A * B1^T
//   blocks with nb0 >= N1 compute C2 = A * B2^T  (column nb0-N1)
// 128x64 tiles, 8x4 per-thread register blocking, double-buffered smem,
// 256 threads, 3 CTAs/SM. Conflict-free smem loads (B at 16B stride).
// Sequential k accumulation -> bit-identical numerics across rounds.
// sym != 0: only blocks with bx <= 2*by+1 computed (Gram symmetry;
//           exactly covers the region mirror_kernel expects).
// Optional epilogue: batchnorm + leaky_relu(0.2).
// Requirements: M % 128 == 0, N % 64 == 0, K % 16 == 0
// ---------------------------------------------------------------------------
#define BM 128
#define BN 64
#define BK 16

__global__ void __launch_bounds__(256, 3)
gemm_nt(const float* __restrict__ A, int lda, long strideA,
        const float* __restrict__ B1, const float* __restrict__ B2,
        int ldb, long strideB,
        float* __restrict__ C1, float* __restrict__ C2,
        int ldc, long strideC,
        int N1, int K,
        const float* __restrict__ bn, int bnN, int sym)
{
    if (sym && (int)blockIdx.x > 2 * (int)blockIdx.y + 1) return;

    __shared__ __align__(16) float As[2][BK][BM];
    __shared__ __align__(16) float Bs[2][BK][BN];

    const int bz = blockIdx.z;
    const int m0 = blockIdx.y * BM;
    const int nb0 = blockIdx.x * BN;

    const float* Bsel;
    float*       Csel;
    int n0;
    if (nb0 < N1) { Bsel = B1; Csel = C1; n0 = nb0; }
    else          { Bsel = B2; Csel = C2; n0 = nb0 - N1; }

    const float* Ab = A    + (long)bz * strideA;
    const float* Bb = Bsel + (long)bz * strideB;
    float*       Cb = Csel + (long)bz * strideC;

    const int tid = threadIdx.x;
    // loader mapping
    const int lr = tid >> 2;            // 0..63
    const int lc = (tid & 3) * 4;       // 0,4,8,12
    // compute mapping: 16x16 thread grid; each thread 8 rows x 4 cols
    const int ty = tid >> 4;            // 0..15
    const int tx = tid & 15;            // 0..15

    float acc[8][4];
#pragma unroll
    for (int i = 0; i < 8; i++)
#pragma unroll
        for (int j = 0; j < 4; j++) acc[i][j] = 0.f;

    const int nTiles = K / BK;
    float4 pa0, pa1, pb0;

    // prefetch tile 0
    pa0 = *reinterpret_cast<const float4*>(&Ab[(long)(m0 + lr)      * lda + lc]);
    pa1 = *reinterpret_cast<const float4*>(&Ab[(long)(m0 + lr + 64) * lda + lc]);
    pb0 = *reinterpret_cast<const float4*>(&Bb[(long)(n0 + lr)      * ldb + lc]);
    As[0][lc + 0][lr] = pa0.x; As[0][lc + 1][lr] = pa0.y;
    As[0][lc + 2][lr] = pa0.z; As[0][lc + 3][lr] = pa0.w;
    As[0][lc + 0][lr + 64] = pa1.x; As[0][lc + 1][lr + 64] = pa1.y;
    As[0][lc + 2][lr + 64] = pa1.z; As[0][lc + 3][lr + 64] = pa1.w;
    Bs[0][lc + 0][lr] = pb0.x; Bs[0][lc + 1][lr] = pb0.y;
    Bs[0][lc + 2][lr] = pb0.z; Bs[0][lc + 3][lr] = pb0.w;
    __syncthreads();

    for (int t = 0; t < nTiles; t++) {
        const int cur = t & 1;
        if (t + 1 < nTiles) {
            const int k0 = (t + 1) * BK;
            pa0 = *reinterpret_cast<const float4*>(&Ab[(long)(m0 + lr)      * lda + k0 + lc]);
            pa1 = *reinterpret_cast<const float4*>(&Ab[(long)(m0 + lr + 64) * lda + k0 + lc]);
            pb0 = *reinterpret_cast<const float4*>(&Bb[(long)(n0 + lr)      * ldb + k0 + lc]);
        }

#pragma unroll
        for (int k = 0; k < BK; k++) {
            float4 a0 = *reinterpret_cast<const float4*>(&As[cur][k][ty * 8]);
            float4 a1 = *reinterpret_cast<const float4*>(&As[cur][k][ty * 8 + 4]);
            float4 b0 = *reinterpret_cast<const float4*>(&Bs[cur][k][tx * 4]);
            float av[8] = {a0.x, a0.y, a0.z, a0.w, a1.x, a1.y, a1.z, a1.w};
            float bv[4] = {b0.x, b0.y, b0.z, b0.w};
#pragma unroll
            for (int i = 0; i < 8; i++)
#pragma unroll
                for (int j = 0; j < 4; j++)
                    acc[i][j] += av[i] * bv[j];
        }

        if (t + 1 < nTiles) {
            const int nxt = 1 - cur;
            As[nxt][lc + 0][lr] = pa0.x; As[nxt][lc + 1][lr] = pa0.y;
            As[nxt][lc + 2][lr] = pa0.z; As[nxt][lc + 3][lr] = pa0.w;
            As[nxt][lc + 0][lr + 64] = pa1.x; As[nxt][lc + 1][lr + 64] = pa1.y;
            As[nxt][lc + 2][lr + 64] = pa1.z; As[nxt][lc + 3][lr + 64] = pa1.w;
            Bs[nxt][lc + 0][lr] = pb0.x; Bs[nxt][lc + 1][lr] = pb0.y;
            Bs[nxt][lc + 2][lr] = pb0.z; Bs[nxt][lc + 3][lr] = pb0.w;
        }
        __syncthreads();
    }

    // epilogue
    const int cm = m0 + ty * 8;
    const int cn = n0 + tx * 4;
    if (bn) {
        float sc[4], sh[4];
#pragma unroll
        for (int j = 0; j < 4; j++) {
            int n = cn + j;
            float g = bn[n], b = bn[bnN + n], m = bn[2 * bnN + n], v = bn[3 * bnN + n];
            sc[j] = g * rsqrtf(v + EPS);
            sh[j] = b - m * sc[j];
        }
#pragma unroll
        for (int i = 0; i < 8; i++) {
#pragma unroll
            for (int j = 0; j < 4; j++) {
                float val = acc[i][j] * sc[j] + sh[j];
                acc[i][j] = val > 0.f ? val : 0.2f * val;
            }
        }
    }
#pragma unroll
    for (int i = 0; i < 8; i++) {
        float4 v0 = make_float4(acc[i][0], acc[i][1], acc[i][2], acc[i][3]);
        *reinterpret_cast<float4*>(&Cb[(long)(cm + i) * ldc + cn]) = v0;
    }
}

// ---------------------------------------------------------------------------
// Gram mirror + diagonal extraction.
// Strictly-upper tiles (m0 >= 128*((n0>>7)+1)): G[n][m] = G[m][n] (bit-exact,
// FMA(a,b,c)==FMA(b,a,c)). Diagonal 32x32 tiles (m0==n0): write g_diag.
// ---------------------------------------------------------------------------
__global__ void mirror_kernel(float* __restrict__ G, float* __restrict__ diag)
{
    int b  = blockIdx.z;
    int m0 = blockIdx.x * 32;   // destination cols
    int n0 = blockIdx.y * 32;   // destination rows
    float* Gb = G + (long)b * NPTS * NPTS;
    int tx = threadIdx.x, ty = threadIdx.y;    // 32 x 8

    if (m0 == n0) {
        // diagonal tile: extract diag (thread row ty==0 covers all 32 cols)
        if (ty == 0)
            diag[b * NPTS + m0 + tx] = Gb[(long)(m0 + tx) * NPTS + m0 + tx];
        return;
    }
    if (m0 < 128 * ((n0 >> 7) + 1)) return;   // tile already computed by gemm

    __shared__ float tile[32][33];
#pragma unroll
    for (int i = 0; i < 32; i += 8)
        tile[ty + i][tx] = Gb[(long)(m0 + ty + i) * NPTS + n0 + tx];
    __syncthreads();
#pragma unroll
    for (int i = 0; i < 32; i += 8)
        Gb[(long)(n0 + ty + i) * NPTS + m0 + tx] = tile[tx][ty + i];
}

// ---------------------------------------------------------------------------
// Top-K (K=20): register-resident two-phase selection.
// key[m] = 2*G[n][m] - G[m][m]; descending value, tie -> lower index.
// ---------------------------------------------------------------------------
__global__ void __launch_bounds__(256)
topk_kernel(const float* __restrict__ G, const float* __restrict__ diag,
            int* __restrict__ idx)
{
    const int b = blockIdx.y;
    const int n = blockIdx.x;
    const float* Gb = G + ((long)b * NPTS + n) * NPTS;
    const float* db = diag + b * NPTS;

    const int tid  = threadIdx.x;
    const int lane = tid & 31;
    const int w    = tid >> 5;          // 0..7
    const int base = w * 128;

    float key[4];
#pragma unroll
    for (int q = 0; q < 4; q++) {
        int m = base + lane + 32 * q;
        key[q] = 2.f * Gb[m] - db[m];
    }

    __shared__ float wv[8][KNN];
    __shared__ int   wi[8][KNN];

    // Phase 1: per-warp top-20 (sorted desc, ties by ascending index)
    for (int it = 0; it < KNN; ++it) {
        float bv = key[0];
        int   bi = base + lane;
#pragma unroll
        for (int q = 1; q < 4; q++) {
            if (key[q] > bv) { bv = key[q]; bi = base + lane + 32 * q; }
        }
#pragma unroll
        for (int off = 16; off > 0; off >>= 1) {
            float ov = __shfl_xor_sync(0xffffffffu, bv, off);
            int   oi = __shfl_xor_sync(0xffffffffu, bi, off);
            if (ov > bv || (ov == bv && oi < bi)) { bv = ov; bi = oi; }
        }
        if (lane == 0) { wv[w][it] = bv; wi[w][it] = bi; }
        const int rel   = bi - base;
        const int l_win = rel & 31;
        const int q_win = rel >> 5;
        if (lane == l_win) {
#pragma unroll
            for (int q = 0; q < 4; q++)
                if (q == q_win) key[q] = -CUDART_INF_F;
        }
    }
    __syncthreads();

    // Phase 2: warp 0 merges 8 sorted lists of 20
    if (w == 0) {
        int ptr = 0;
        int* orow = idx + ((long)b * NPTS + n) * KNN;
        for (int it = 0; it < KNN; ++it) {
            float v = (lane < 8) ? wv[lane][ptr] : -CUDART_INF_F;
            int   i = (lane < 8) ? wi[lane][ptr] : 0x7fffffff;
            int   j = lane;
#pragma unroll
            for (int off = 4; off > 0; off >>= 1) {
                float ov = __shfl_xor_sync(0xffffffffu, v, off);
                int   oi = __shfl_xor_sync(0xffffffffu, i, off);
                int   oj = __shfl_xor_sync(0xffffffffu, j, off);
                if (ov > v || (ov == v && oi < i)) { v = ov; i = oi; j = oj; }
            }
            if (lane == 0) orow[it] = i;
            if (lane < 8 && lane == j) ptr++;
        }
    }
}

// ---------------------------------------------------------------------------
// EdgeConv aggregation (float4 across channels):
// out[n][o] = bn_lrelu( max_k U[idx[n,k]][o]  -  U[n][o] + V[n][o] )
// (valid because bn scale > 0 and leaky_relu are monotone increasing)
// ---------------------------------------------------------------------------
__global__ void __launch_bounds__(256)
aggregate_kernel(const float* __restrict__ U, const float* __restrict__ V,
                 const int* __restrict__ idx, const float* __restrict__ bn,
                 float* __restrict__ out, int O, int ldo)
{
    int b = blockIdx.y, n = blockIdx.x;
    __shared__ int nb[KNN];
    int tid = threadIdx.x;
    if (tid < KNN) nb[tid] = idx[((long)b * NPTS + n) * KNN + tid];
    __syncthreads();

    const float* Ub = U + (long)b * NPTS * O;
    const float* un = Ub + (long)n * O;
    const float* vn = V + ((long)b * NPTS + n) * O;
    float*       on = out + ((long)b * NPTS + n) * ldo;

    const int O4 = O >> 2;
    for (int o4 = tid; o4 < O4; o4 += 256) {
        float4 mx = make_float4(-CUDART_INF_F, -CUDART_INF_F, -CUDART_INF_F, -CUDART_INF_F);
#pragma unroll
        for (int k = 0; k < KNN; k++) {
            float4 u = *reinterpret_cast<const float4*>(&Ub[(long)nb[k] * O + o4 * 4]);
            mx.x = fmaxf(mx.x, u.x); mx.y = fmaxf(mx.y, u.y);
            mx.z = fmaxf(mx.z, u.z); mx.w = fmaxf(mx.w, u.w);
        }
        float4 uo = *reinterpret_cast<const float4*>(&un[o4 * 4]);
        float4 vo = *reinterpret_cast<const float4*>(&vn[o4 * 4]);
        float4 gg = *reinterpret_cast<const float4*>(&bn[o4 * 4]);
        float4 be = *reinterpret_cast<const float4*>(&bn[O + o4 * 4]);
        float4 mm = *reinterpret_cast<const float4*>(&bn[2 * O + o4 * 4]);
        float4 vv = *reinterpret_cast<const float4*>(&bn[3 * O + o4 * 4]);
        float y0 = mx.x - uo.x + vo.x, y1 = mx.y - uo.y + vo.y;
        float y2 = mx.z - uo.z + vo.z, y3 = mx.w - uo.w + vo.w;
        float s0 = gg.x * rsqrtf(vv.x + EPS), s1 = gg.y * rsqrtf(vv.y + EPS);
        float s2 = gg.z * rsqrtf(vv.z + EPS), s3 = gg.w * rsqrtf(vv.w + EPS);
        y0 = (y0 - mm.x) * s0 + be.x; y1 = (y1 - mm.y) * s1 + be.y;
        y2 = (y2 - mm.z) * s2 + be.z; y3 = (y3 - mm.w) * s3 + be.w;
        float4 r;
        r.x = y0 > 0.f ? y0 : 0.2f * y0;
        r.y = y1 > 0.f ? y1 : 0.2f * y1;
        r.z = y2 > 0.f ? y2 : 0.2f * y2;
        r.w = y3 > 0.f ? y3 : 0.2f * y3;
        *reinterpret_cast<float4*>(&on[o4 * 4]) = r;
    }
}

// ---------------------------------------------------------------------------
// Pooling (max + mean over N), two-stage
// ---------------------------------------------------------------------------
__global__ void __launch_bounds__(256)
pool1_kernel(const float* __restrict__ H5, float* __restrict__ pmax, float* __restrict__ psum)
{
    int b = blockIdx.y, chunk = blockIdx.x;      // PCH chunks of 32 rows
    int tid = threadIdx.x;
    float mx[4] = {-CUDART_INF_F, -CUDART_INF_F, -CUDART_INF_F, -CUDART_INF_F};
    float sm[4] = {0.f, 0.f, 0.f, 0.f};
    const float* h = H5 + ((long)b * NPTS + chunk * 32) * 1024;
    for (int n = 0; n < 32; n++) {
        const float* row = h + (long)n * 1024;
#pragma unroll
        for (int q = 0; q < 4; q++) {
            float v = row[tid + 256 * q];
            mx[q] = fmaxf(mx[q], v);
            sm[q] += v;
        }
    }
#pragma unroll
    for (int q = 0; q < 4; q++) {
        int o = tid + 256 * q;
        pmax[((long)b * PCH + chunk) * 1024 + o] = mx[q];
        psum[((long)b * PCH + chunk) * 1024 + o] = sm[q];
    }
}

__global__ void __launch_bounds__(256)
pool2_kernel(const float* __restrict__ pmax, const float* __restrict__ psum,
             float* __restrict__ pooled)
{
    int b = blockIdx.y;
    int o = blockIdx.x * 256 + threadIdx.x;      // 0..1023
    float mx = -CUDART_INF_F, sm = 0.f;
    for (int c = 0; c < PCH; c++) {
        mx = fmaxf(mx, pmax[((long)b * PCH + c) * 1024 + o]);
        sm += psum[((long)b * PCH + c) * 1024 + o];
    }
    pooled[b * 2048 + o]        = mx;
    pooled[b * 2048 + 1024 + o] = sm * (1.f / NPTS);
}

// ---------------------------------------------------------------------------
// Head:  z = bn_lrelu(pooled @ Wl1^T);  out = z @ Wl3^T + bl3
// ---------------------------------------------------------------------------
__global__ void __launch_bounds__(256)
head1_kernel(const float* __restrict__ pooled, const float* __restrict__ Wl1,
             const float* __restrict__ bn6, float* __restrict__ z)
{
    int b = blockIdx.y, j = blockIdx.x;          // j < 512
    int tid = threadIdx.x;
    const float* p = pooled + b * 2048;
    const float* w = Wl1 + (long)j * 2048;
    float s = 0.f;
    for (int c = tid; c < 2048; c += 256) s += p[c] * w[c];
    __shared__ float red[256];
    red[tid] = s; __syncthreads();
    for (int st = 128; st > 0; st >>= 1) {
        if (tid < st) red[tid] += red[tid + st];
        __syncthreads();
    }
    if (tid == 0) {
        float y = red[0];
        float g = bn6[j], be = bn6[512 + j], mm = bn6[1024 + j], vv = bn6[1536 + j];
        y = (y - mm) * (g * rsqrtf(vv + EPS)) + be;
        z[b * 512 + j] = y > 0.f ? y : 0.2f * y;
    }
}

__global__ void __launch_bounds__(128)
head2_kernel(const float* __restrict__ z, const float* __restrict__ Wl3,
             const float* __restrict__ bl3, float* __restrict__ out)
{
    int b = blockIdx.y, t = blockIdx.x;          // t < 40
    int tid = threadIdx.x;
    const float* zb = z + b * 512;
    const float* w  = Wl3 + (long)t * 512;
    float s = 0.f;
    for (int c = tid; c < 512; c += 128) s += zb[c] * w[c];
    __shared__ float red[128];
    red[tid] = s; __syncthreads();
    for (int st = 64; st > 0; st >>= 1) {
        if (tid < st) red[tid] += red[tid + st];
        __syncthreads();
    }
    if (tid == 0) out[b * 40 + t] = red[0] + bl3[t];
}

// ---------------------------------------------------------------------------
// Host driver. A side stream runs the U/V GEMM concurrently with the
// gram -> mirror/diag -> topk chain (they share only the input x_i).
// The fork event is recorded right after the previous stage completes on the
// main stream, BEFORE the gram launch, so uv truly overlaps gram. uv is
// ISSUED after the topk chain only to control ncu's launch-index (the 4th
// kernel launch is now topk1); graph dependencies are unchanged.
// ---------------------------------------------------------------------------
static cudaStream_t s_side = nullptr;
static cudaEvent_t  s_fork[4], s_join[4];

static void ensure_side_stream()
{
    if (!s_side) {
        cudaStreamCreateWithFlags(&s_side, cudaStreamNonBlocking);
        for (int i = 0; i < 4; i++) {
            cudaEventCreateWithFlags(&s_fork[i], cudaEventDisableTiming);
            cudaEventCreateWithFlags(&s_join[i], cudaEventDisableTiming);
        }
    }
}

static void launch_gemm2(cudaStream_t st,
                         const float* A, int lda, long sA,
                         const float* B1, const float* B2, int ldb, long sB,
                         float* C1, float* C2, int ldc, long sC,
                         int M, int N1, int N2, int K,
                         const float* bn, int bnN, int sym)
{
    dim3 grid((N1 + N2) / BN, M / BM, BATCH);
    gemm_nt<<<grid, 256, 0, st>>>(A, lda, sA, B1, B2, ldb, sB, C1, C2, ldc, sC,
                                  N1, K, bn, bnN, sym);
}

static void run_edgeconv(int ci, const float* Xin, int lda, int Kdim,
                         const float* W, const float* bn, int O,
                         float* Hout, int ldo,
                         float* G, float* diag, int* idx, float* U, float* V)
{
    // fork point: side stream may start as soon as Xin is ready
    cudaEventRecord(s_fork[ci], 0);
    cudaStreamWaitEvent(s_side, s_fork[ci], 0);

    // main stream: gram (lower-triangular block region) -> mirror+diag -> topk
    launch_gemm2(0, Xin, lda, (long)NPTS * lda, Xin, Xin, lda, (long)NPTS * lda,
                 G, G, NPTS, (long)NPTS * NPTS, NPTS, NPTS, 0, Kdim, nullptr, 0, 1);
    mirror_kernel<<<dim3(NPTS / 32, NPTS / 32, BATCH), dim3(32, 8)>>>(G, diag);
    topk_kernel<<<dim3(NPTS, BATCH), 256>>>(G, diag, idx);

    // side stream: fused U/V gemm (depends only on the fork event)
    launch_gemm2(s_side, Xin, lda, (long)NPTS * lda, W, W + Kdim, 2 * Kdim, 0,
                 U, V, O, (long)NPTS * O, NPTS, O, O, Kdim, nullptr, 0, 0);
    cudaEventRecord(s_join[ci], s_side);

    // join: aggregation needs both topk (main) and U/V (side)
    cudaStreamWaitEvent(0, s_join[ci], 0);
    aggregate_kernel<<<dim3(NPTS, BATCH), 256>>>(U, V, idx, bn, Hout, O, ldo);
}

extern "C" void kernel_launch(void* const* d_in, const int* in_sizes, int n_in,
                              void* d_out, int out_size)
{
    (void)in_sizes; (void)n_in; (void)out_size;
    const float* x   = (const float*)d_in[0];
    const float* W1  = (const float*)d_in[1];
    const float* bn1 = (const float*)d_in[2];
    const float* W2  = (const float*)d_in[3];
    const float* bn2 = (const float*)d_in[4];
    const float* W3  = (const float*)d_in[5];
    const float* bn3 = (const float*)d_in[6];
    const float* W4  = (const float*)d_in[7];
    const float* bn4 = (const float*)d_in[8];
    const float* W5  = (const float*)d_in[9];
    const float* bn5 = (const float*)d_in[10];
    const float* Wl1 = (const float*)d_in[11];
    const float* bn6 = (const float*)d_in[12];
    const float* Wl3 = (const float*)d_in[13];
    const float* bl3 = (const float*)d_in[14];
    float* out = (float*)d_out;

    ensure_side_stream();

    float *XT, *G, *diag, *U, *V, *H, *H5, *pmax, *psum, *pool, *z;
    int* idx;
    cudaGetSymbolAddress((void**)&XT,   g_XT);
    cudaGetSymbolAddress((void**)&G,    g_G);
    cudaGetSymbolAddress((void**)&diag, g_diag);
    cudaGetSymbolAddress((void**)&idx,  g_idx);
    cudaGetSymbolAddress((void**)&U,    g_U);
    cudaGetSymbolAddress((void**)&V,    g_V);
    cudaGetSymbolAddress((void**)&H,    g_H);
    cudaGetSymbolAddress((void**)&H5,   g_H5);
    cudaGetSymbolAddress((void**)&pmax, g_pmax);
    cudaGetSymbolAddress((void**)&psum, g_psum);
    cudaGetSymbolAddress((void**)&pool, g_pool);
    cudaGetSymbolAddress((void**)&z,    g_z);

    // transpose x (B,C,N) -> XT (B,N,C)
    transpose_kernel<<<dim3(NPTS / 32, CIN / 32, BATCH), dim3(32, 8)>>>(x, XT);

    // EdgeConv 1..4, outputs written into slices of H (ld = 1152)
    run_edgeconv(0, XT,      CIN,  768, W1, bn1, 512, H,       HDIM, G, diag, idx, U, V);
    run_edgeconv(1, H,       HDIM, 512, W2, bn2, 256, H + 512, HDIM, G, diag, idx, U, V);
    run_edgeconv(2, H + 512, HDIM, 256, W3, bn3, 128, H + 768, HDIM, G, diag, idx, U, V);
    run_edgeconv(3, H + 768, HDIM, 128, W4, bn4, 256, H + 896, HDIM, G, diag, idx, U, V);

    // conv5: H (N x 1152) @ W5^T (1152 x 1024) + bn5 + lrelu  -> H5
    launch_gemm2(0, H, HDIM, (long)NPTS * HDIM, W5, W5, HDIM, 0,
                 H5, H5, 1024, (long)NPTS * 1024, NPTS, 1024, 0, HDIM, bn5, 1024, 0);

    // pooling -> pooled (B x 2048)
    pool1_kernel<<<dim3(PCH, BATCH), 256>>>(H5, pmax, psum);
    pool2_kernel<<<dim3(4, BATCH), 256>>>(pmax, psum, pool);

    // head
    head1_kernel<<<dim3(512, BATCH), 256>>>(pool, Wl1, bn6, z);
    head2_kernel<<<dim3(40, BATCH), 128>>>(z, Wl3, bl3, out);
}

// round 15
// speedup vs baseline: 1.5308x; 1.2069x over previous
#include <cuda_runtime.h>
#include <math_constants.h>

// ---------------------------------------------------------------------------
// Problem constants
// ---------------------------------------------------------------------------
#define BATCH 4
#define NPTS  1024
#define CIN   768
#define KNN   20
#define HDIM  1152    // 512 + 256 + 128 + 256
#define PCH   32      // pooling chunks
#define EPS   1e-5f

// ---------------------------------------------------------------------------
// Scratch (device globals; no allocation allowed)
// ---------------------------------------------------------------------------
__device__ float g_XT [BATCH * NPTS * CIN];     // x transposed: (B, N, C)
__device__ float g_G  [BATCH * NPTS * NPTS];    // gram matrix
__device__ float g_diag[BATCH * NPTS];          // gram diagonal
__device__ int   g_idx[BATCH * NPTS * KNN];     // knn indices
__device__ float g_U  [BATCH * NPTS * 512];     // W_left  @ x
__device__ float g_V  [BATCH * NPTS * 512];     // W_right @ x
__device__ float g_H  [BATCH * NPTS * HDIM];    // concat(x1,x2,x3,x4)
__device__ float g_H5 [BATCH * NPTS * 1024];    // conv5 output
__device__ float g_pmax[BATCH * PCH * 1024];
__device__ float g_psum[BATCH * PCH * 1024];
__device__ float g_pool[BATCH * 2048];
__device__ float g_z   [BATCH * 512];

// ---------------------------------------------------------------------------
// Transpose: x (B, C, N) -> XT (B, N, C)
// ---------------------------------------------------------------------------
__global__ void transpose_kernel(const float* __restrict__ x, float* __restrict__ xt) {
    __shared__ float tile[32][33];
    int b  = blockIdx.z;
    int c0 = blockIdx.y * 32;
    int n0 = blockIdx.x * 32;
    const float* xb  = x  + (long)b * CIN * NPTS;
    float*       xtb = xt + (long)b * NPTS * CIN;
    int tx = threadIdx.x, ty = threadIdx.y;            // 32 x 8
#pragma unroll
    for (int i = 0; i < 32; i += 8)
        tile[ty + i][tx] = xb[(long)(c0 + ty + i) * NPTS + n0 + tx];
    __syncthreads();
#pragma unroll
    for (int i = 0; i < 32; i += 8)
        xtb[(long)(n0 + ty + i) * CIN + c0 + tx] = tile[tx][ty + i];
}

// ---------------------------------------------------------------------------
// Tiled SGEMM with dual-source N split (measured 34.4 TF/s config):
//   blocks with nb0 <  N1 compute C1 = A * B1^T
//   blocks with nb0 >= N1 compute C2 = A * B2^T  (column nb0-N1)
// 128x64 tiles, 8x4 per-thread register blocking, double-buffered smem,
// 256 threads, 3 CTAs/SM. Conflict-free smem loads (B at 16B stride).
// Sequential k accumulation -> bit-identical numerics across rounds.
// sym != 0: only blocks with bx <= 2*by+1 computed (Gram symmetry;
//           exactly covers the region mirror_kernel expects).
// Optional epilogue: batchnorm + leaky_relu(0.2).
// Requirements: M % 128 == 0, N % 64 == 0, K % 16 == 0
// ---------------------------------------------------------------------------
#define BM 128
#define BN 64
#define BK 16

__global__ void __launch_bounds__(256, 3)
gemm_nt(const float* __restrict__ A, int lda, long strideA,
        const float* __restrict__ B1, const float* __restrict__ B2,
        int ldb, long strideB,
        float* __restrict__ C1, float* __restrict__ C2,
        int ldc, long strideC,
        int N1, int K,
        const float* __restrict__ bn, int bnN, int sym)
{
    if (sym && (int)blockIdx.x > 2 * (int)blockIdx.y + 1) return;

    __shared__ __align__(16) float As[2][BK][BM];
    __shared__ __align__(16) float Bs[2][BK][BN];

    const int bz = blockIdx.z;
    const int m0 = blockIdx.y * BM;
    const int nb0 = blockIdx.x * BN;

    const float* Bsel;
    float*       Csel;
    int n0;
    if (nb0 < N1) { Bsel = B1; Csel = C1; n0 = nb0; }
    else          { Bsel = B2; Csel = C2; n0 = nb0 - N1; }

    const float* Ab = A    + (long)bz * strideA;
    const float* Bb = Bsel + (long)bz * strideB;
    float*       Cb = Csel + (long)bz * strideC;

    const int tid = threadIdx.x;
    // loader mapping
    const int lr = tid >> 2;            // 0..63
    const int lc = (tid & 3) * 4;       // 0,4,8,12
    // compute mapping: 16x16 thread grid; each thread 8 rows x 4 cols
    const int ty = tid >> 4;            // 0..15
    const int tx = tid & 15;            // 0..15

    float acc[8][4];
#pragma unroll
    for (int i = 0; i < 8; i++)
#pragma unroll
        for (int j = 0; j < 4; j++) acc[i][j] = 0.f;

    const int nTiles = K / BK;
    float4 pa0, pa1, pb0;

    // prefetch tile 0
    pa0 = *reinterpret_cast<const float4*>(&Ab[(long)(m0 + lr)      * lda + lc]);
    pa1 = *reinterpret_cast<const float4*>(&Ab[(long)(m0 + lr + 64) * lda + lc]);
    pb0 = *reinterpret_cast<const float4*>(&Bb[(long)(n0 + lr)      * ldb + lc]);
    As[0][lc + 0][lr] = pa0.x; As[0][lc + 1][lr] = pa0.y;
    As[0][lc + 2][lr] = pa0.z; As[0][lc + 3][lr] = pa0.w;
    As[0][lc + 0][lr + 64] = pa1.x; As[0][lc + 1][lr + 64] = pa1.y;
    As[0][lc + 2][lr + 64] = pa1.z; As[0][lc + 3][lr + 64] = pa1.w;
    Bs[0][lc + 0][lr] = pb0.x; Bs[0][lc + 1][lr] = pb0.y;
    Bs[0][lc + 2][lr] = pb0.z; Bs[0][lc + 3][lr] = pb0.w;
    __syncthreads();

    for (int t = 0; t < nTiles; t++) {
        const int cur = t & 1;
        if (t + 1 < nTiles) {
            const int k0 = (t + 1) * BK;
            pa0 = *reinterpret_cast<const float4*>(&Ab[(long)(m0 + lr)      * lda + k0 + lc]);
            pa1 = *reinterpret_cast<const float4*>(&Ab[(long)(m0 + lr + 64) * lda + k0 + lc]);
            pb0 = *reinterpret_cast<const float4*>(&Bb[(long)(n0 + lr)      * ldb + k0 + lc]);
        }

#pragma unroll
        for (int k = 0; k < BK; k++) {
            float4 a0 = *reinterpret_cast<const float4*>(&As[cur][k][ty * 8]);
            float4 a1 = *reinterpret_cast<const float4*>(&As[cur][k][ty * 8 + 4]);
            float4 b0 = *reinterpret_cast<const float4*>(&Bs[cur][k][tx * 4]);
            float av[8] = {a0.x, a0.y, a0.z, a0.w, a1.x, a1.y, a1.z, a1.w};
            float bv[4] = {b0.x, b0.y, b0.z, b0.w};
#pragma unroll
            for (int i = 0; i < 8; i++)
#pragma unroll
                for (int j = 0; j < 4; j++)
                    acc[i][j] += av[i] * bv[j];
        }

        if (t + 1 < nTiles) {
            const int nxt = 1 - cur;
            As[nxt][lc + 0][lr] = pa0.x; As[nxt][lc + 1][lr] = pa0.y;
            As[nxt][lc + 2][lr] = pa0.z; As[nxt][lc + 3][lr] = pa0.w;
            As[nxt][lc + 0][lr + 64] = pa1.x; As[nxt][lc + 1][lr + 64] = pa1.y;
            As[nxt][lc + 2][lr + 64] = pa1.z; As[nxt][lc + 3][lr + 64] = pa1.w;
            Bs[nxt][lc + 0][lr] = pb0.x; Bs[nxt][lc + 1][lr] = pb0.y;
            Bs[nxt][lc + 2][lr] = pb0.z; Bs[nxt][lc + 3][lr] = pb0.w;
        }
        __syncthreads();
    }

    // epilogue
    const int cm = m0 + ty * 8;
    const int cn = n0 + tx * 4;
    if (bn) {
        float sc[4], sh[4];
#pragma unroll
        for (int j = 0; j < 4; j++) {
            int n = cn + j;
            float g = bn[n], b = bn[bnN + n], m = bn[2 * bnN + n], v = bn[3 * bnN + n];
            sc[j] = g * rsqrtf(v + EPS);
            sh[j] = b - m * sc[j];
        }
#pragma unroll
        for (int i = 0; i < 8; i++) {
#pragma unroll
            for (int j = 0; j < 4; j++) {
                float val = acc[i][j] * sc[j] + sh[j];
                acc[i][j] = val > 0.f ? val : 0.2f * val;
            }
        }
    }
#pragma unroll
    for (int i = 0; i < 8; i++) {
        float4 v0 = make_float4(acc[i][0], acc[i][1], acc[i][2], acc[i][3]);
        *reinterpret_cast<float4*>(&Cb[(long)(cm + i) * ldc + cn]) = v0;
    }
}

// ---------------------------------------------------------------------------
// Gram mirror + diagonal extraction.
// ---------------------------------------------------------------------------
__global__ void mirror_kernel(float* __restrict__ G, float* __restrict__ diag)
{
    int b  = blockIdx.z;
    int m0 = blockIdx.x * 32;   // destination cols
    int n0 = blockIdx.y * 32;   // destination rows
    float* Gb = G + (long)b * NPTS * NPTS;
    int tx = threadIdx.x, ty = threadIdx.y;    // 32 x 8

    if (m0 == n0) {
        if (ty == 0)
            diag[b * NPTS + m0 + tx] = Gb[(long)(m0 + tx) * NPTS + m0 + tx];
        return;
    }
    if (m0 < 128 * ((n0 >> 7) + 1)) return;   // tile already computed by gemm

    __shared__ float tile[32][33];
#pragma unroll
    for (int i = 0; i < 32; i += 8)
        tile[ty + i][tx] = Gb[(long)(m0 + ty + i) * NPTS + n0 + tx];
    __syncthreads();
#pragma unroll
    for (int i = 0; i < 32; i += 8)
        Gb[(long)(n0 + ty + i) * NPTS + m0 + tx] = tile[tx][ty + i];
}

// ---------------------------------------------------------------------------
// Top-K (K=20) via exact 4-pass radix select.
// key[m] = 2*G[n][m] - G[m][m], mapped to an order-preserving u32.
// Selected SET = top-20 by (value desc, index asc) — identical to the
// previous comparator semantics. Output order is irrelevant: the only
// consumer (aggregate) takes a max over the 20 neighbors.
// 4 histogram levels (8 bits each) find the exact 20th value T and the
// residual count r; collection takes all u > T plus the r lowest-index
// elements with u == T.
// ---------------------------------------------------------------------------
__global__ void __launch_bounds__(256)
topk_kernel(const float* __restrict__ G, const float* __restrict__ diag,
            int* __restrict__ idx)
{
    const int b = blockIdx.y;
    const int n = blockIdx.x;
    const float* Gb = G + ((long)b * NPTS + n) * NPTS;
    const float* db = diag + b * NPTS;

    const int tid  = threadIdx.x;
    const int lane = tid & 31;
    const int w    = tid >> 5;

    // load 4 keys, map to sortable u32 (monotone: bigger float -> bigger u32)
    unsigned u[4];
#pragma unroll
    for (int q = 0; q < 4; q++) {
        int m = tid + 256 * q;
        float key = 2.f * Gb[m] - db[m];
        unsigned ub = __float_as_uint(key);
        u[q] = (ub & 0x80000000u) ? ~ub : (ub | 0x80000000u);
    }

    __shared__ unsigned hist[256];
    __shared__ unsigned sB, sK;
    __shared__ int outcnt, tcnt;
    __shared__ int tie[NPTS];

    if (tid == 0) { sK = KNN; outcnt = 0; tcnt = 0; }

    unsigned prefix = 0;
#pragma unroll
    for (int level = 0; level < 4; level++) {
        const int shift = 24 - 8 * level;
        hist[tid] = 0;
        __syncthreads();                  // publishes prev sB/sK + clears
        const unsigned kcur = sK;
#pragma unroll
        for (int q = 0; q < 4; q++) {
            bool active = (level == 0) || ((u[q] >> (shift + 8)) == prefix);
            if (active) atomicAdd(&hist[(u[q] >> shift) & 0xFFu], 1u);
        }
        __syncthreads();
        if (w == 0) {
            // lane owns bins [8*lane, 8*lane+8)
            unsigned h[8], ls[8];
#pragma unroll
            for (int p = 0; p < 8; p++) h[p] = hist[lane * 8 + p];
            ls[7] = h[7];
#pragma unroll
            for (int p = 6; p >= 0; p--) ls[p] = h[p] + ls[p + 1];
            unsigned inc = ls[0];
#pragma unroll
            for (int off = 1; off < 32; off <<= 1) {
                unsigned vv = __shfl_down_sync(0xffffffffu, inc, off);
                if (lane + off < 32) inc += vv;
            }
            const unsigned above = inc - ls[0];     // sum over lanes > lane
#pragma unroll
            for (int p = 0; p < 8; p++) {
                unsigned sb = ls[p] + above;
                unsigned sn = ((p < 7) ? ls[p + 1] : 0u) + above;
                if (sb >= kcur && sn < kcur) {
                    sB = lane * 8 + p;
                    sK = kcur - sn;
                }
            }
        }
        __syncthreads();
        prefix = (prefix << 8) | sB;
    }

    const unsigned T = prefix;            // exact 20th-largest key (as u32)
    int* orow = idx + ((long)b * NPTS + n) * KNN;

#pragma unroll
    for (int q = 0; q < 4; q++) {
        int m = tid + 256 * q;
        if (u[q] > T) {
            int p = atomicAdd(&outcnt, 1);
            orow[p] = m;
        } else if (u[q] == T) {
            int p = atomicAdd(&tcnt, 1);
            tie[p] = m;
        }
    }
    __syncthreads();
    if (tid == 0) {
        int c = outcnt;                   // == KNN - sK
        int r = (int)sK;                  // ties to take (lowest indices)
        int tn = tcnt;
        for (int s = 0; s < r; s++) {
            int best = 0x7fffffff, bj = -1;
            for (int j = 0; j < tn; j++)
                if (tie[j] < best) { best = tie[j]; bj = j; }
            tie[bj] = 0x7fffffff;
            orow[c + s] = best;
        }
    }
}

// ---------------------------------------------------------------------------
// EdgeConv aggregation (float4 across channels):
// out[n][o] = bn_lrelu( max_k U[idx[n,k]][o]  -  U[n][o] + V[n][o] )
// ---------------------------------------------------------------------------
__global__ void __launch_bounds__(256)
aggregate_kernel(const float* __restrict__ U, const float* __restrict__ V,
                 const int* __restrict__ idx, const float* __restrict__ bn,
                 float* __restrict__ out, int O, int ldo)
{
    int b = blockIdx.y, n = blockIdx.x;
    __shared__ int nb[KNN];
    int tid = threadIdx.x;
    if (tid < KNN) nb[tid] = idx[((long)b * NPTS + n) * KNN + tid];
    __syncthreads();

    const float* Ub = U + (long)b * NPTS * O;
    const float* un = Ub + (long)n * O;
    const float* vn = V + ((long)b * NPTS + n) * O;
    float*       on = out + ((long)b * NPTS + n) * ldo;

    const int O4 = O >> 2;
    for (int o4 = tid; o4 < O4; o4 += 256) {
        float4 mx = make_float4(-CUDART_INF_F, -CUDART_INF_F, -CUDART_INF_F, -CUDART_INF_F);
#pragma unroll
        for (int k = 0; k < KNN; k++) {
            float4 u = *reinterpret_cast<const float4*>(&Ub[(long)nb[k] * O + o4 * 4]);
            mx.x = fmaxf(mx.x, u.x); mx.y = fmaxf(mx.y, u.y);
            mx.z = fmaxf(mx.z, u.z); mx.w = fmaxf(mx.w, u.w);
        }
        float4 uo = *reinterpret_cast<const float4*>(&un[o4 * 4]);
        float4 vo = *reinterpret_cast<const float4*>(&vn[o4 * 4]);
        float4 gg = *reinterpret_cast<const float4*>(&bn[o4 * 4]);
        float4 be = *reinterpret_cast<const float4*>(&bn[O + o4 * 4]);
        float4 mm = *reinterpret_cast<const float4*>(&bn[2 * O + o4 * 4]);
        float4 vv = *reinterpret_cast<const float4*>(&bn[3 * O + o4 * 4]);
        float y0 = mx.x - uo.x + vo.x, y1 = mx.y - uo.y + vo.y;
        float y2 = mx.z - uo.z + vo.z, y3 = mx.w - uo.w + vo.w;
        float s0 = gg.x * rsqrtf(vv.x + EPS), s1 = gg.y * rsqrtf(vv.y + EPS);
        float s2 = gg.z * rsqrtf(vv.z + EPS), s3 = gg.w * rsqrtf(vv.w + EPS);
        y0 = (y0 - mm.x) * s0 + be.x; y1 = (y1 - mm.y) * s1 + be.y;
        y2 = (y2 - mm.z) * s2 + be.z; y3 = (y3 - mm.w) * s3 + be.w;
        float4 r;
        r.x = y0 > 0.f ? y0 : 0.2f * y0;
        r.y = y1 > 0.f ? y1 : 0.2f * y1;
        r.z = y2 > 0.f ? y2 : 0.2f * y2;
        r.w = y3 > 0.f ? y3 : 0.2f * y3;
        *reinterpret_cast<float4*>(&on[o4 * 4]) = r;
    }
}

// ---------------------------------------------------------------------------
// Pooling (max + mean over N), two-stage
// ---------------------------------------------------------------------------
__global__ void __launch_bounds__(256)
pool1_kernel(const float* __restrict__ H5, float* __restrict__ pmax, float* __restrict__ psum)
{
    int b = blockIdx.y, chunk = blockIdx.x;      // PCH chunks of 32 rows
    int tid = threadIdx.x;
    float mx[4] = {-CUDART_INF_F, -CUDART_INF_F, -CUDART_INF_F, -CUDART_INF_F};
    float sm[4] = {0.f, 0.f, 0.f, 0.f};
    const float* h = H5 + ((long)b * NPTS + chunk * 32) * 1024;
    for (int n = 0; n < 32; n++) {
        const float* row = h + (long)n * 1024;
#pragma unroll
        for (int q = 0; q < 4; q++) {
            float v = row[tid + 256 * q];
            mx[q] = fmaxf(mx[q], v);
            sm[q] += v;
        }
    }
#pragma unroll
    for (int q = 0; q < 4; q++) {
        int o = tid + 256 * q;
        pmax[((long)b * PCH + chunk) * 1024 + o] = mx[q];
        psum[((long)b * PCH + chunk) * 1024 + o] = sm[q];
    }
}

__global__ void __launch_bounds__(256)
pool2_kernel(const float* __restrict__ pmax, const float* __restrict__ psum,
             float* __restrict__ pooled)
{
    int b = blockIdx.y;
    int o = blockIdx.x * 256 + threadIdx.x;      // 0..1023
    float mx = -CUDART_INF_F, sm = 0.f;
    for (int c = 0; c < PCH; c++) {
        mx = fmaxf(mx, pmax[((long)b * PCH + c) * 1024 + o]);
        sm += psum[((long)b * PCH + c) * 1024 + o];
    }
    pooled[b * 2048 + o]        = mx;
    pooled[b * 2048 + 1024 + o] = sm * (1.f / NPTS);
}

// ---------------------------------------------------------------------------
// Head:  z = bn_lrelu(pooled @ Wl1^T);  out = z @ Wl3^T + bl3
// ---------------------------------------------------------------------------
__global__ void __launch_bounds__(256)
head1_kernel(const float* __restrict__ pooled, const float* __restrict__ Wl1,
             const float* __restrict__ bn6, float* __restrict__ z)
{
    int b = blockIdx.y, j = blockIdx.x;          // j < 512
    int tid = threadIdx.x;
    const float* p = pooled + b * 2048;
    const float* w = Wl1 + (long)j * 2048;
    float s = 0.f;
    for (int c = tid; c < 2048; c += 256) s += p[c] * w[c];
    __shared__ float red[256];
    red[tid] = s; __syncthreads();
    for (int st = 128; st > 0; st >>= 1) {
        if (tid < st) red[tid] += red[tid + st];
        __syncthreads();
    }
    if (tid == 0) {
        float y = red[0];
        float g = bn6[j], be = bn6[512 + j], mm = bn6[1024 + j], vv = bn6[1536 + j];
        y = (y - mm) * (g * rsqrtf(vv + EPS)) + be;
        z[b * 512 + j] = y > 0.f ? y : 0.2f * y;
    }
}

__global__ void __launch_bounds__(128)
head2_kernel(const float* __restrict__ z, const float* __restrict__ Wl3,
             const float* __restrict__ bl3, float* __restrict__ out)
{
    int b = blockIdx.y, t = blockIdx.x;          // t < 40
    int tid = threadIdx.x;
    const float* zb = z + b * 512;
    const float* w  = Wl3 + (long)t * 512;
    float s = 0.f;
    for (int c = tid; c < 512; c += 128) s += zb[c] * w[c];
    __shared__ float red[128];
    red[tid] = s; __syncthreads();
    for (int st = 64; st > 0; st >>= 1) {
        if (tid < st) red[tid] += red[tid + st];
        __syncthreads();
    }
    if (tid == 0) out[b * 40 + t] = red[0] + bl3[t];
}

// ---------------------------------------------------------------------------
// Host driver. A side stream runs the U/V GEMM concurrently with the
// gram -> mirror/diag -> topk chain (they share only the input x_i).
// ---------------------------------------------------------------------------
static cudaStream_t s_side = nullptr;
static cudaEvent_t  s_fork[4], s_join[4];

static void ensure_side_stream()
{
    if (!s_side) {
        cudaStreamCreateWithFlags(&s_side, cudaStreamNonBlocking);
        for (int i = 0; i < 4; i++) {
            cudaEventCreateWithFlags(&s_fork[i], cudaEventDisableTiming);
            cudaEventCreateWithFlags(&s_join[i], cudaEventDisableTiming);
        }
    }
}

static void launch_gemm2(cudaStream_t st,
                         const float* A, int lda, long sA,
                         const float* B1, const float* B2, int ldb, long sB,
                         float* C1, float* C2, int ldc, long sC,
                         int M, int N1, int N2, int K,
                         const float* bn, int bnN, int sym)
{
    dim3 grid((N1 + N2) / BN, M / BM, BATCH);
    gemm_nt<<<grid, 256, 0, st>>>(A, lda, sA, B1, B2, ldb, sB, C1, C2, ldc, sC,
                                  N1, K, bn, bnN, sym);
}

static void run_edgeconv(int ci, const float* Xin, int lda, int Kdim,
                         const float* W, const float* bn, int O,
                         float* Hout, int ldo,
                         float* G, float* diag, int* idx, float* U, float* V)
{
    // fork point: side stream may start as soon as Xin is ready
    cudaEventRecord(s_fork[ci], 0);
    cudaStreamWaitEvent(s_side, s_fork[ci], 0);

    // main stream: gram (lower-triangular block region) -> mirror+diag -> topk
    launch_gemm2(0, Xin, lda, (long)NPTS * lda, Xin, Xin, lda, (long)NPTS * lda,
                 G, G, NPTS, (long)NPTS * NPTS, NPTS, NPTS, 0, Kdim, nullptr, 0, 1);
    mirror_kernel<<<dim3(NPTS / 32, NPTS / 32, BATCH), dim3(32, 8)>>>(G, diag);
    topk_kernel<<<dim3(NPTS, BATCH), 256>>>(G, diag, idx);

    // side stream: fused U/V gemm (depends only on the fork event)
    launch_gemm2(s_side, Xin, lda, (long)NPTS * lda, W, W + Kdim, 2 * Kdim, 0,
                 U, V, O, (long)NPTS * O, NPTS, O, O, Kdim, nullptr, 0, 0);
    cudaEventRecord(s_join[ci], s_side);

    // join: aggregation needs both topk (main) and U/V (side)
    cudaStreamWaitEvent(0, s_join[ci], 0);
    aggregate_kernel<<<dim3(NPTS, BATCH), 256>>>(U, V, idx, bn, Hout, O, ldo);
}

extern "C" void kernel_launch(void* const* d_in, const int* in_sizes, int n_in,
                              void* d_out, int out_size)
{
    (void)in_sizes; (void)n_in; (void)out_size;
    const float* x   = (const float*)d_in[0];
    const float* W1  = (const float*)d_in[1];
    const float* bn1 = (const float*)d_in[2];
    const float* W2  = (const float*)d_in[3];
    const float* bn2 = (const float*)d_in[4];
    const float* W3  = (const float*)d_in[5];
    const float* bn3 = (const float*)d_in[6];
    const float* W4  = (const float*)d_in[7];
    const float* bn4 = (const float*)d_in[8];
    const float* W5  = (const float*)d_in[9];
    const float* bn5 = (const float*)d_in[10];
    const float* Wl1 = (const float*)d_in[11];
    const float* bn6 = (const float*)d_in[12];
    const float* Wl3 = (const float*)d_in[13];
    const float* bl3 = (const float*)d_in[14];
    float* out = (float*)d_out;

    ensure_side_stream();

    float *XT, *G, *diag, *U, *V, *H, *H5, *pmax, *psum, *pool, *z;
    int* idx;
    cudaGetSymbolAddress((void**)&XT,   g_XT);
    cudaGetSymbolAddress((void**)&G,    g_G);
    cudaGetSymbolAddress((void**)&diag, g_diag);
    cudaGetSymbolAddress((void**)&idx,  g_idx);
    cudaGetSymbolAddress((void**)&U,    g_U);
    cudaGetSymbolAddress((void**)&V,    g_V);
    cudaGetSymbolAddress((void**)&H,    g_H);
    cudaGetSymbolAddress((void**)&H5,   g_H5);
    cudaGetSymbolAddress((void**)&pmax, g_pmax);
    cudaGetSymbolAddress((void**)&psum, g_psum);
    cudaGetSymbolAddress((void**)&pool, g_pool);
    cudaGetSymbolAddress((void**)&z,    g_z);

    // transpose x (B,C,N) -> XT (B,N,C)
    transpose_kernel<<<dim3(NPTS / 32, CIN / 32, BATCH), dim3(32, 8)>>>(x, XT);

    // EdgeConv 1..4, outputs written into slices of H (ld = 1152)
    run_edgeconv(0, XT,      CIN,  768, W1, bn1, 512, H,       HDIM, G, diag, idx, U, V);
    run_edgeconv(1, H,       HDIM, 512, W2, bn2, 256, H + 512, HDIM, G, diag, idx, U, V);
    run_edgeconv(2, H + 512, HDIM, 256, W3, bn3, 128, H + 768, HDIM, G, diag, idx, U, V);
    run_edgeconv(3, H + 768, HDIM, 128, W4, bn4, 256, H + 896, HDIM, G, diag, idx, U, V);

    // conv5: H (N x 1152) @ W5^T (1152 x 1024) + bn5 + lrelu  -> H5
    launch_gemm2(0, H, HDIM, (long)NPTS * HDIM, W5, W5, HDIM, 0,
                 H5, H5, 1024, (long)NPTS * 1024, NPTS, 1024, 0, HDIM, bn5, 1024, 0);

    // pooling -> pooled (B x 2048)
    pool1_kernel<<<dim3(PCH, BATCH), 256>>>(H5, pmax, psum);
    pool2_kernel<<<dim3(4, BATCH), 256>>>(pmax, psum, pool);

    // head
    head1_kernel<<<dim3(512, BATCH), 256>>>(pool, Wl1, bn6, z);
    head2_kernel<<<dim3(40, BATCH), 128>>>(z, Wl3, bl3, out);
}

// round 17
// speedup vs baseline: 1.6575x; 1.0828x over previous
#include <cuda_runtime.h>
#include <cuda_bf16.h>
#include <mma.h>
#include <math_constants.h>

using namespace nvcuda;

// ---------------------------------------------------------------------------
// Problem constants
// ---------------------------------------------------------------------------
#define BATCH 4
#define NPTS  1024
#define CIN   768
#define KNN   20
#define HDIM  1152    // 512 + 256 + 128 + 256
#define PCH   32      // pooling chunks
#define EPS   1e-5f
#define MTOT  (BATCH * NPTS)   // 4096 rows of H / H5

// ---------------------------------------------------------------------------
// Scratch (device globals; no allocation allowed)
// ---------------------------------------------------------------------------
__device__ float g_XT [BATCH * NPTS * CIN];
__device__ float g_G  [BATCH * NPTS * NPTS];
__device__ float g_diag[BATCH * NPTS];
__device__ int   g_idx[BATCH * NPTS * KNN];
__device__ float g_U  [BATCH * NPTS * 512];
__device__ float g_V  [BATCH * NPTS * 512];
__device__ float g_H  [BATCH * NPTS * HDIM];
__device__ float g_H5 [BATCH * NPTS * 1024];
__device__ float g_pmax[BATCH * PCH * 1024];
__device__ float g_psum[BATCH * PCH * 1024];
__device__ float g_pool[BATCH * 2048];
__device__ float g_z   [BATCH * 512];
// bf16 split buffers (uint4 arrays force 16B alignment)
__device__ uint4 g_Hhi4[MTOT * HDIM / 8];
__device__ uint4 g_Hlo4[MTOT * HDIM / 8];
__device__ uint4 g_Whi4[1024 * HDIM / 8];
__device__ uint4 g_Wlo4[1024 * HDIM / 8];

// ---------------------------------------------------------------------------
// Transpose: x (B, C, N) -> XT (B, N, C)
// ---------------------------------------------------------------------------
__global__ void transpose_kernel(const float* __restrict__ x, float* __restrict__ xt) {
    __shared__ float tile[32][33];
    int b  = blockIdx.z;
    int c0 = blockIdx.y * 32;
    int n0 = blockIdx.x * 32;
    const float* xb  = x  + (long)b * CIN * NPTS;
    float*       xtb = xt + (long)b * NPTS * CIN;
    int tx = threadIdx.x, ty = threadIdx.y;
#pragma unroll
    for (int i = 0; i < 32; i += 8)
        tile[ty + i][tx] = xb[(long)(c0 + ty + i) * NPTS + n0 + tx];
    __syncthreads();
#pragma unroll
    for (int i = 0; i < 32; i += 8)
        xtb[(long)(n0 + ty + i) * CIN + c0 + tx] = tile[tx][ty + i];
}

// ---------------------------------------------------------------------------
// Scalar fp32 SGEMM (measured 34.4 TF/s) — unchanged (Gram must stay bit-exact)
// ---------------------------------------------------------------------------
#define BM 128
#define BN 64
#define BK 16

__global__ void __launch_bounds__(256, 3)
gemm_nt(const float* __restrict__ A, int lda, long strideA,
        const float* __restrict__ B1, const float* __restrict__ B2,
        int ldb, long strideB,
        float* __restrict__ C1, float* __restrict__ C2,
        int ldc, long strideC,
        int N1, int K,
        const float* __restrict__ bn, int bnN, int sym)
{
    if (sym && (int)blockIdx.x > 2 * (int)blockIdx.y + 1) return;

    __shared__ __align__(16) float As[2][BK][BM];
    __shared__ __align__(16) float Bs[2][BK][BN];

    const int bz = blockIdx.z;
    const int m0 = blockIdx.y * BM;
    const int nb0 = blockIdx.x * BN;

    const float* Bsel;
    float*       Csel;
    int n0;
    if (nb0 < N1) { Bsel = B1; Csel = C1; n0 = nb0; }
    else          { Bsel = B2; Csel = C2; n0 = nb0 - N1; }

    const float* Ab = A    + (long)bz * strideA;
    const float* Bb = Bsel + (long)bz * strideB;
    float*       Cb = Csel + (long)bz * strideC;

    const int tid = threadIdx.x;
    const int lr = tid >> 2;
    const int lc = (tid & 3) * 4;
    const int ty = tid >> 4;
    const int tx = tid & 15;

    float acc[8][4];
#pragma unroll
    for (int i = 0; i < 8; i++)
#pragma unroll
        for (int j = 0; j < 4; j++) acc[i][j] = 0.f;

    const int nTiles = K / BK;
    float4 pa0, pa1, pb0;

    pa0 = *reinterpret_cast<const float4*>(&Ab[(long)(m0 + lr)      * lda + lc]);
    pa1 = *reinterpret_cast<const float4*>(&Ab[(long)(m0 + lr + 64) * lda + lc]);
    pb0 = *reinterpret_cast<const float4*>(&Bb[(long)(n0 + lr)      * ldb + lc]);
    As[0][lc + 0][lr] = pa0.x; As[0][lc + 1][lr] = pa0.y;
    As[0][lc + 2][lr] = pa0.z; As[0][lc + 3][lr] = pa0.w;
    As[0][lc + 0][lr + 64] = pa1.x; As[0][lc + 1][lr + 64] = pa1.y;
    As[0][lc + 2][lr + 64] = pa1.z; As[0][lc + 3][lr + 64] = pa1.w;
    Bs[0][lc + 0][lr] = pb0.x; Bs[0][lc + 1][lr] = pb0.y;
    Bs[0][lc + 2][lr] = pb0.z; Bs[0][lc + 3][lr] = pb0.w;
    __syncthreads();

    for (int t = 0; t < nTiles; t++) {
        const int cur = t & 1;
        if (t + 1 < nTiles) {
            const int k0 = (t + 1) * BK;
            pa0 = *reinterpret_cast<const float4*>(&Ab[(long)(m0 + lr)      * lda + k0 + lc]);
            pa1 = *reinterpret_cast<const float4*>(&Ab[(long)(m0 + lr + 64) * lda + k0 + lc]);
            pb0 = *reinterpret_cast<const float4*>(&Bb[(long)(n0 + lr)      * ldb + k0 + lc]);
        }

#pragma unroll
        for (int k = 0; k < BK; k++) {
            float4 a0 = *reinterpret_cast<const float4*>(&As[cur][k][ty * 8]);
            float4 a1 = *reinterpret_cast<const float4*>(&As[cur][k][ty * 8 + 4]);
            float4 b0 = *reinterpret_cast<const float4*>(&Bs[cur][k][tx * 4]);
            float av[8] = {a0.x, a0.y, a0.z, a0.w, a1.x, a1.y, a1.z, a1.w};
            float bv[4] = {b0.x, b0.y, b0.z, b0.w};
#pragma unroll
            for (int i = 0; i < 8; i++)
#pragma unroll
                for (int j = 0; j < 4; j++)
                    acc[i][j] += av[i] * bv[j];
        }

        if (t + 1 < nTiles) {
            const int nxt = 1 - cur;
            As[nxt][lc + 0][lr] = pa0.x; As[nxt][lc + 1][lr] = pa0.y;
            As[nxt][lc + 2][lr] = pa0.z; As[nxt][lc + 3][lr] = pa0.w;
            As[nxt][lc + 0][lr + 64] = pa1.x; As[nxt][lc + 1][lr + 64] = pa1.y;
            As[nxt][lc + 2][lr + 64] = pa1.z; As[nxt][lc + 3][lr + 64] = pa1.w;
            Bs[nxt][lc + 0][lr] = pb0.x; Bs[nxt][lc + 1][lr] = pb0.y;
            Bs[nxt][lc + 2][lr] = pb0.z; Bs[nxt][lc + 3][lr] = pb0.w;
        }
        __syncthreads();
    }

    const int cm = m0 + ty * 8;
    const int cn = n0 + tx * 4;
    if (bn) {
        float sc[4], sh[4];
#pragma unroll
        for (int j = 0; j < 4; j++) {
            int n = cn + j;
            float g = bn[n], b = bn[bnN + n], m = bn[2 * bnN + n], v = bn[3 * bnN + n];
            sc[j] = g * rsqrtf(v + EPS);
            sh[j] = b - m * sc[j];
        }
#pragma unroll
        for (int i = 0; i < 8; i++) {
#pragma unroll
            for (int j = 0; j < 4; j++) {
                float val = acc[i][j] * sc[j] + sh[j];
                acc[i][j] = val > 0.f ? val : 0.2f * val;
            }
        }
    }
#pragma unroll
    for (int i = 0; i < 8; i++) {
        float4 v0 = make_float4(acc[i][0], acc[i][1], acc[i][2], acc[i][3]);
        *reinterpret_cast<float4*>(&Cb[(long)(cm + i) * ldc + cn]) = v0;
    }
}

// ---------------------------------------------------------------------------
// Gram mirror + diagonal extraction
// ---------------------------------------------------------------------------
__global__ void mirror_kernel(float* __restrict__ G, float* __restrict__ diag)
{
    int b  = blockIdx.z;
    int m0 = blockIdx.x * 32;
    int n0 = blockIdx.y * 32;
    float* Gb = G + (long)b * NPTS * NPTS;
    int tx = threadIdx.x, ty = threadIdx.y;

    if (m0 == n0) {
        if (ty == 0)
            diag[b * NPTS + m0 + tx] = Gb[(long)(m0 + tx) * NPTS + m0 + tx];
        return;
    }
    if (m0 < 128 * ((n0 >> 7) + 1)) return;

    __shared__ float tile[32][33];
#pragma unroll
    for (int i = 0; i < 32; i += 8)
        tile[ty + i][tx] = Gb[(long)(m0 + ty + i) * NPTS + n0 + tx];
    __syncthreads();
#pragma unroll
    for (int i = 0; i < 32; i += 8)
        Gb[(long)(n0 + ty + i) * NPTS + m0 + tx] = tile[tx][ty + i];
}

// ---------------------------------------------------------------------------
// Top-K via exact 4-pass radix select (measured 21 us) — unchanged
// ---------------------------------------------------------------------------
__global__ void __launch_bounds__(256)
topk_kernel(const float* __restrict__ G, const float* __restrict__ diag,
            int* __restrict__ idx)
{
    const int b = blockIdx.y;
    const int n = blockIdx.x;
    const float* Gb = G + ((long)b * NPTS + n) * NPTS;
    const float* db = diag + b * NPTS;

    const int tid  = threadIdx.x;
    const int lane = tid & 31;
    const int w    = tid >> 5;

    unsigned u[4];
#pragma unroll
    for (int q = 0; q < 4; q++) {
        int m = tid + 256 * q;
        float key = 2.f * Gb[m] - db[m];
        unsigned ub = __float_as_uint(key);
        u[q] = (ub & 0x80000000u) ? ~ub : (ub | 0x80000000u);
    }

    __shared__ unsigned hist[256];
    __shared__ unsigned sB, sK;
    __shared__ int outcnt, tcnt;
    __shared__ int tie[NPTS];

    if (tid == 0) { sK = KNN; outcnt = 0; tcnt = 0; }

    unsigned prefix = 0;
#pragma unroll
    for (int level = 0; level < 4; level++) {
        const int shift = 24 - 8 * level;
        hist[tid] = 0;
        __syncthreads();
        const unsigned kcur = sK;
#pragma unroll
        for (int q = 0; q < 4; q++) {
            bool active = (level == 0) || ((u[q] >> (shift + 8)) == prefix);
            if (active) atomicAdd(&hist[(u[q] >> shift) & 0xFFu], 1u);
        }
        __syncthreads();
        if (w == 0) {
            unsigned h[8], ls[8];
#pragma unroll
            for (int p = 0; p < 8; p++) h[p] = hist[lane * 8 + p];
            ls[7] = h[7];
#pragma unroll
            for (int p = 6; p >= 0; p--) ls[p] = h[p] + ls[p + 1];
            unsigned inc = ls[0];
#pragma unroll
            for (int off = 1; off < 32; off <<= 1) {
                unsigned vv = __shfl_down_sync(0xffffffffu, inc, off);
                if (lane + off < 32) inc += vv;
            }
            const unsigned above = inc - ls[0];
#pragma unroll
            for (int p = 0; p < 8; p++) {
                unsigned sb = ls[p] + above;
                unsigned sn = ((p < 7) ? ls[p + 1] : 0u) + above;
                if (sb >= kcur && sn < kcur) {
                    sB = lane * 8 + p;
                    sK = kcur - sn;
                }
            }
        }
        __syncthreads();
        prefix = (prefix << 8) | sB;
    }

    const unsigned T = prefix;
    int* orow = idx + ((long)b * NPTS + n) * KNN;

#pragma unroll
    for (int q = 0; q < 4; q++) {
        int m = tid + 256 * q;
        if (u[q] > T) {
            int p = atomicAdd(&outcnt, 1);
            orow[p] = m;
        } else if (u[q] == T) {
            int p = atomicAdd(&tcnt, 1);
            tie[p] = m;
        }
    }
    __syncthreads();
    if (tid == 0) {
        int c = outcnt;
        int r = (int)sK;
        int tn = tcnt;
        for (int s = 0; s < r; s++) {
            int best = 0x7fffffff, bj = -1;
            for (int j = 0; j < tn; j++)
                if (tie[j] < best) { best = tie[j]; bj = j; }
            tie[bj] = 0x7fffffff;
            orow[c + s] = best;
        }
    }
}

// ---------------------------------------------------------------------------
// EdgeConv aggregation (float4) — unchanged
// ---------------------------------------------------------------------------
__global__ void __launch_bounds__(256)
aggregate_kernel(const float* __restrict__ U, const float* __restrict__ V,
                 const int* __restrict__ idx, const float* __restrict__ bn,
                 float* __restrict__ out, int O, int ldo)
{
    int b = blockIdx.y, n = blockIdx.x;
    __shared__ int nb[KNN];
    int tid = threadIdx.x;
    if (tid < KNN) nb[tid] = idx[((long)b * NPTS + n) * KNN + tid];
    __syncthreads();

    const float* Ub = U + (long)b * NPTS * O;
    const float* un = Ub + (long)n * O;
    const float* vn = V + ((long)b * NPTS + n) * O;
    float*       on = out + ((long)b * NPTS + n) * ldo;

    const int O4 = O >> 2;
    for (int o4 = tid; o4 < O4; o4 += 256) {
        float4 mx = make_float4(-CUDART_INF_F, -CUDART_INF_F, -CUDART_INF_F, -CUDART_INF_F);
#pragma unroll
        for (int k = 0; k < KNN; k++) {
            float4 u = *reinterpret_cast<const float4*>(&Ub[(long)nb[k] * O + o4 * 4]);
            mx.x = fmaxf(mx.x, u.x); mx.y = fmaxf(mx.y, u.y);
            mx.z = fmaxf(mx.z, u.z); mx.w = fmaxf(mx.w, u.w);
        }
        float4 uo = *reinterpret_cast<const float4*>(&un[o4 * 4]);
        float4 vo = *reinterpret_cast<const float4*>(&vn[o4 * 4]);
        float4 gg = *reinterpret_cast<const float4*>(&bn[o4 * 4]);
        float4 be = *reinterpret_cast<const float4*>(&bn[O + o4 * 4]);
        float4 mm = *reinterpret_cast<const float4*>(&bn[2 * O + o4 * 4]);
        float4 vv = *reinterpret_cast<const float4*>(&bn[3 * O + o4 * 4]);
        float y0 = mx.x - uo.x + vo.x, y1 = mx.y - uo.y + vo.y;
        float y2 = mx.z - uo.z + vo.z, y3 = mx.w - uo.w + vo.w;
        float s0 = gg.x * rsqrtf(vv.x + EPS), s1 = gg.y * rsqrtf(vv.y + EPS);
        float s2 = gg.z * rsqrtf(vv.z + EPS), s3 = gg.w * rsqrtf(vv.w + EPS);
        y0 = (y0 - mm.x) * s0 + be.x; y1 = (y1 - mm.y) * s1 + be.y;
        y2 = (y2 - mm.z) * s2 + be.z; y3 = (y3 - mm.w) * s3 + be.w;
        float4 r;
        r.x = y0 > 0.f ? y0 : 0.2f * y0;
        r.y = y1 > 0.f ? y1 : 0.2f * y1;
        r.z = y2 > 0.f ? y2 : 0.2f * y2;
        r.w = y3 > 0.f ? y3 : 0.2f * y3;
        *reinterpret_cast<float4*>(&on[o4 * 4]) = r;
    }
}

// ---------------------------------------------------------------------------
// bf16 split:  hi = bf16(v), lo = bf16(v - float(hi))
// ---------------------------------------------------------------------------
__global__ void split_kernel(const float* __restrict__ src,
                             __nv_bfloat16* __restrict__ hi,
                             __nv_bfloat16* __restrict__ lo, int n)
{
    int i = blockIdx.x * 256 + threadIdx.x;
    if (i < n) {
        float v = src[i];
        __nv_bfloat16 h = __float2bfloat16(v);
        hi[i] = h;
        lo[i] = __float2bfloat16(v - __bfloat162float(h));
    }
}

// ---------------------------------------------------------------------------
// conv5 via wmma bf16 split-GEMM (legacy tensor path, valid on sm_100):
//   H5 = bn_lrelu( (Hhi+Hlo) @ (Whi+Wlo)^T )  ~=  Ahi*Bhi + Ahi*Blo + Alo*Bhi
// fp32 accumulators. M=4096, N=1024, K=1152.
// Block tile 128x64, 8 warps (4x2), warp tile 32x32 = 2x2 wmma 16x16x16 frags.
// K staged through smem in 16-wide chunks (72 iters), ld = 24 bf16 (48 B).
// Epilogue staged through smem (128x68 floats) -> bn+lrelu -> coalesced store.
// ---------------------------------------------------------------------------
#define WLD 24                       // smem row length in bf16 (16 + 8 pad)
#define A_HI_OFF 0                   // 128*24*2 = 6144 bytes
#define A_LO_OFF 6144
#define B_HI_OFF 12288               // 64*24*2 = 3072 bytes
#define B_LO_OFF 15360
#define SMEM_BYTES 36864             // >= 18432 (tiles) and >= 34816 (stage 128*68*4)
#define STG_LD 68

__global__ void __launch_bounds__(256)
wmma_conv5_kernel(const __nv_bfloat16* __restrict__ Hhi,
                  const __nv_bfloat16* __restrict__ Hlo,
                  const __nv_bfloat16* __restrict__ Whi,
                  const __nv_bfloat16* __restrict__ Wlo,
                  const float* __restrict__ bn,
                  float* __restrict__ H5)
{
    __shared__ __align__(16) char smbuf[SMEM_BYTES];
    __nv_bfloat16* sAhi = reinterpret_cast<__nv_bfloat16*>(smbuf + A_HI_OFF);
    __nv_bfloat16* sAlo = reinterpret_cast<__nv_bfloat16*>(smbuf + A_LO_OFF);
    __nv_bfloat16* sBhi = reinterpret_cast<__nv_bfloat16*>(smbuf + B_HI_OFF);
    __nv_bfloat16* sBlo = reinterpret_cast<__nv_bfloat16*>(smbuf + B_LO_OFF);
    float* stage = reinterpret_cast<float*>(smbuf);

    const int tid = threadIdx.x;
    const int wid = tid >> 5;
    const int wm  = wid >> 1;          // 0..3 -> rows wm*32
    const int wn  = wid & 1;           // 0..1 -> cols wn*32
    const int m0 = blockIdx.y * 128;
    const int n0 = blockIdx.x * 64;

    wmma::fragment<wmma::accumulator, 16, 16, 16, float> acc[2][2];
#pragma unroll
    for (int i = 0; i < 2; i++)
#pragma unroll
        for (int j = 0; j < 2; j++) wmma::fill_fragment(acc[i][j], 0.f);

    const int ar = tid >> 1;           // 0..127 (A row)
    const int ah = (tid & 1) * 8;      // 0 or 8 (col half)
    const int br = (tid & 127) >> 1;   // 0..63 (B row)
    const int bh = (tid & 1) * 8;

    for (int kc = 0; kc < HDIM; kc += 16) {
        // stage A: 128 x 16 (hi and lo)
        {
            long g = (long)(m0 + ar) * HDIM + kc + ah;
            *reinterpret_cast<uint4*>(&sAhi[ar * WLD + ah]) =
                *reinterpret_cast<const uint4*>(Hhi + g);
            *reinterpret_cast<uint4*>(&sAlo[ar * WLD + ah]) =
                *reinterpret_cast<const uint4*>(Hlo + g);
        }
        // stage B: 64 x 16 (threads < 128: hi, threads >= 128: lo)
        {
            long g = (long)(n0 + br) * HDIM + kc + bh;
            if (tid < 128)
                *reinterpret_cast<uint4*>(&sBhi[br * WLD + bh]) =
                    *reinterpret_cast<const uint4*>(Whi + g);
            else
                *reinterpret_cast<uint4*>(&sBlo[br * WLD + bh]) =
                    *reinterpret_cast<const uint4*>(Wlo + g);
        }
        __syncthreads();

        wmma::fragment<wmma::matrix_a, 16, 16, 16, __nv_bfloat16, wmma::row_major> fahi[2], falo[2];
        wmma::fragment<wmma::matrix_b, 16, 16, 16, __nv_bfloat16, wmma::col_major> fbhi[2], fblo[2];
#pragma unroll
        for (int i = 0; i < 2; i++) {
            wmma::load_matrix_sync(fahi[i], &sAhi[(wm * 32 + i * 16) * WLD], WLD);
            wmma::load_matrix_sync(falo[i], &sAlo[(wm * 32 + i * 16) * WLD], WLD);
        }
#pragma unroll
        for (int j = 0; j < 2; j++) {
            wmma::load_matrix_sync(fbhi[j], &sBhi[(wn * 32 + j * 16) * WLD], WLD);
            wmma::load_matrix_sync(fblo[j], &sBlo[(wn * 32 + j * 16) * WLD], WLD);
        }
#pragma unroll
        for (int i = 0; i < 2; i++)
#pragma unroll
            for (int j = 0; j < 2; j++) {
                wmma::mma_sync(acc[i][j], fahi[i], fbhi[j], acc[i][j]);
                wmma::mma_sync(acc[i][j], fahi[i], fblo[j], acc[i][j]);
                wmma::mma_sync(acc[i][j], falo[i], fbhi[j], acc[i][j]);
            }
        __syncthreads();
    }

    // epilogue: stage 128x64 tile in smem, then bn+lrelu + coalesced store
#pragma unroll
    for (int i = 0; i < 2; i++)
#pragma unroll
        for (int j = 0; j < 2; j++)
            wmma::store_matrix_sync(&stage[(wm * 32 + i * 16) * STG_LD + wn * 32 + j * 16],
                                    acc[i][j], STG_LD, wmma::mem_row_major);
    __syncthreads();

    {
        const int r = tid >> 1;            // 0..127
        const int h = (tid & 1) * 32;      // col half offset
        float* orow = H5 + (long)(m0 + r) * 1024 + n0 + h;
#pragma unroll
        for (int c4 = 0; c4 < 8; c4++) {
            float4 o;
            float y;
            int nc = n0 + h + c4 * 4;
            float v0 = stage[r * STG_LD + h + c4 * 4 + 0];
            float v1 = stage[r * STG_LD + h + c4 * 4 + 1];
            float v2 = stage[r * STG_LD + h + c4 * 4 + 2];
            float v3 = stage[r * STG_LD + h + c4 * 4 + 3];
            float s0 = bn[nc + 0] * rsqrtf(bn[3072 + nc + 0] + EPS);
            float s1 = bn[nc + 1] * rsqrtf(bn[3072 + nc + 1] + EPS);
            float s2 = bn[nc + 2] * rsqrtf(bn[3072 + nc + 2] + EPS);
            float s3 = bn[nc + 3] * rsqrtf(bn[3072 + nc + 3] + EPS);
            y = (v0 - bn[2048 + nc + 0]) * s0 + bn[1024 + nc + 0]; o.x = y > 0.f ? y : 0.2f * y;
            y = (v1 - bn[2048 + nc + 1]) * s1 + bn[1024 + nc + 1]; o.y = y > 0.f ? y : 0.2f * y;
            y = (v2 - bn[2048 + nc + 2]) * s2 + bn[1024 + nc + 2]; o.z = y > 0.f ? y : 0.2f * y;
            y = (v3 - bn[2048 + nc + 3]) * s3 + bn[1024 + nc + 3]; o.w = y > 0.f ? y : 0.2f * y;
            *reinterpret_cast<float4*>(orow + c4 * 4) = o;
        }
    }
}

// ---------------------------------------------------------------------------
// Pooling (max + mean over N), two-stage — unchanged
// ---------------------------------------------------------------------------
__global__ void __launch_bounds__(256)
pool1_kernel(const float* __restrict__ H5, float* __restrict__ pmax, float* __restrict__ psum)
{
    int b = blockIdx.y, chunk = blockIdx.x;
    int tid = threadIdx.x;
    float mx[4] = {-CUDART_INF_F, -CUDART_INF_F, -CUDART_INF_F, -CUDART_INF_F};
    float sm[4] = {0.f, 0.f, 0.f, 0.f};
    const float* h = H5 + ((long)b * NPTS + chunk * 32) * 1024;
    for (int n = 0; n < 32; n++) {
        const float* row = h + (long)n * 1024;
#pragma unroll
        for (int q = 0; q < 4; q++) {
            float v = row[tid + 256 * q];
            mx[q] = fmaxf(mx[q], v);
            sm[q] += v;
        }
    }
#pragma unroll
    for (int q = 0; q < 4; q++) {
        int o = tid + 256 * q;
        pmax[((long)b * PCH + chunk) * 1024 + o] = mx[q];
        psum[((long)b * PCH + chunk) * 1024 + o] = sm[q];
    }
}

__global__ void __launch_bounds__(256)
pool2_kernel(const float* __restrict__ pmax, const float* __restrict__ psum,
             float* __restrict__ pooled)
{
    int b = blockIdx.y;
    int o = blockIdx.x * 256 + threadIdx.x;
    float mx = -CUDART_INF_F, sm = 0.f;
    for (int c = 0; c < PCH; c++) {
        mx = fmaxf(mx, pmax[((long)b * PCH + c) * 1024 + o]);
        sm += psum[((long)b * PCH + c) * 1024 + o];
    }
    pooled[b * 2048 + o]        = mx;
    pooled[b * 2048 + 1024 + o] = sm * (1.f / NPTS);
}

// ---------------------------------------------------------------------------
// Head — unchanged
// ---------------------------------------------------------------------------
__global__ void __launch_bounds__(256)
head1_kernel(const float* __restrict__ pooled, const float* __restrict__ Wl1,
             const float* __restrict__ bn6, float* __restrict__ z)
{
    int b = blockIdx.y, j = blockIdx.x;
    int tid = threadIdx.x;
    const float* p = pooled + b * 2048;
    const float* w = Wl1 + (long)j * 2048;
    float s = 0.f;
    for (int c = tid; c < 2048; c += 256) s += p[c] * w[c];
    __shared__ float red[256];
    red[tid] = s; __syncthreads();
    for (int st = 128; st > 0; st >>= 1) {
        if (tid < st) red[tid] += red[tid + st];
        __syncthreads();
    }
    if (tid == 0) {
        float y = red[0];
        float g = bn6[j], be = bn6[512 + j], mm = bn6[1024 + j], vv = bn6[1536 + j];
        y = (y - mm) * (g * rsqrtf(vv + EPS)) + be;
        z[b * 512 + j] = y > 0.f ? y : 0.2f * y;
    }
}

__global__ void __launch_bounds__(128)
head2_kernel(const float* __restrict__ z, const float* __restrict__ Wl3,
             const float* __restrict__ bl3, float* __restrict__ out)
{
    int b = blockIdx.y, t = blockIdx.x;
    int tid = threadIdx.x;
    const float* zb = z + b * 512;
    const float* w  = Wl3 + (long)t * 512;
    float s = 0.f;
    for (int c = tid; c < 512; c += 128) s += zb[c] * w[c];
    __shared__ float red[128];
    red[tid] = s; __syncthreads();
    for (int st = 64; st > 0; st >>= 1) {
        if (tid < st) red[tid] += red[tid + st];
        __syncthreads();
    }
    if (tid == 0) out[b * 40 + t] = red[0] + bl3[t];
}

// ---------------------------------------------------------------------------
// Host driver
// ---------------------------------------------------------------------------
static cudaStream_t s_side = nullptr;
static cudaEvent_t  s_fork[4], s_join[4];

static void ensure_side_stream()
{
    if (!s_side) {
        cudaStreamCreateWithFlags(&s_side, cudaStreamNonBlocking);
        for (int i = 0; i < 4; i++) {
            cudaEventCreateWithFlags(&s_fork[i], cudaEventDisableTiming);
            cudaEventCreateWithFlags(&s_join[i], cudaEventDisableTiming);
        }
    }
}

static void launch_gemm2(cudaStream_t st,
                         const float* A, int lda, long sA,
                         const float* B1, const float* B2, int ldb, long sB,
                         float* C1, float* C2, int ldc, long sC,
                         int M, int N1, int N2, int K,
                         const float* bn, int bnN, int sym)
{
    dim3 grid((N1 + N2) / BN, M / BM, BATCH);
    gemm_nt<<<grid, 256, 0, st>>>(A, lda, sA, B1, B2, ldb, sB, C1, C2, ldc, sC,
                                  N1, K, bn, bnN, sym);
}

static void run_edgeconv(int ci, const float* Xin, int lda, int Kdim,
                         const float* W, const float* bn, int O,
                         float* Hout, int ldo,
                         float* G, float* diag, int* idx, float* U, float* V)
{
    cudaEventRecord(s_fork[ci], 0);
    cudaStreamWaitEvent(s_side, s_fork[ci], 0);

    launch_gemm2(0, Xin, lda, (long)NPTS * lda, Xin, Xin, lda, (long)NPTS * lda,
                 G, G, NPTS, (long)NPTS * NPTS, NPTS, NPTS, 0, Kdim, nullptr, 0, 1);
    mirror_kernel<<<dim3(NPTS / 32, NPTS / 32, BATCH), dim3(32, 8)>>>(G, diag);
    topk_kernel<<<dim3(NPTS, BATCH), 256>>>(G, diag, idx);

    launch_gemm2(s_side, Xin, lda, (long)NPTS * lda, W, W + Kdim, 2 * Kdim, 0,
                 U, V, O, (long)NPTS * O, NPTS, O, O, Kdim, nullptr, 0, 0);
    cudaEventRecord(s_join[ci], s_side);

    cudaStreamWaitEvent(0, s_join[ci], 0);
    aggregate_kernel<<<dim3(NPTS, BATCH), 256>>>(U, V, idx, bn, Hout, O, ldo);
}

extern "C" void kernel_launch(void* const* d_in, const int* in_sizes, int n_in,
                              void* d_out, int out_size)
{
    (void)in_sizes; (void)n_in; (void)out_size;
    const float* x   = (const float*)d_in[0];
    const float* W1  = (const float*)d_in[1];
    const float* bn1 = (const float*)d_in[2];
    const float* W2  = (const float*)d_in[3];
    const float* bn2 = (const float*)d_in[4];
    const float* W3  = (const float*)d_in[5];
    const float* bn3 = (const float*)d_in[6];
    const float* W4  = (const float*)d_in[7];
    const float* bn4 = (const float*)d_in[8];
    const float* W5  = (const float*)d_in[9];
    const float* bn5 = (const float*)d_in[10];
    const float* Wl1 = (const float*)d_in[11];
    const float* bn6 = (const float*)d_in[12];
    const float* Wl3 = (const float*)d_in[13];
    const float* bl3 = (const float*)d_in[14];
    float* out = (float*)d_out;

    ensure_side_stream();

    float *XT, *G, *diag, *U, *V, *H, *H5, *pmax, *psum, *pool, *z;
    int* idx;
    __nv_bfloat16 *Hhi, *Hlo, *Whi, *Wlo;
    cudaGetSymbolAddress((void**)&XT,   g_XT);
    cudaGetSymbolAddress((void**)&G,    g_G);
    cudaGetSymbolAddress((void**)&diag, g_diag);
    cudaGetSymbolAddress((void**)&idx,  g_idx);
    cudaGetSymbolAddress((void**)&U,    g_U);
    cudaGetSymbolAddress((void**)&V,    g_V);
    cudaGetSymbolAddress((void**)&H,    g_H);
    cudaGetSymbolAddress((void**)&H5,   g_H5);
    cudaGetSymbolAddress((void**)&pmax, g_pmax);
    cudaGetSymbolAddress((void**)&psum, g_psum);
    cudaGetSymbolAddress((void**)&pool, g_pool);
    cudaGetSymbolAddress((void**)&z,    g_z);
    cudaGetSymbolAddress((void**)&Hhi,  g_Hhi4);
    cudaGetSymbolAddress((void**)&Hlo,  g_Hlo4);
    cudaGetSymbolAddress((void**)&Whi,  g_Whi4);
    cudaGetSymbolAddress((void**)&Wlo,  g_Wlo4);

    // W5 split (no dependencies, cheap) — issued early on the side stream path
    split_kernel<<<(1024 * HDIM + 255) / 256, 256>>>(W5, Whi, Wlo, 1024 * HDIM);

    // transpose x (B,C,N) -> XT (B,N,C)
    transpose_kernel<<<dim3(NPTS / 32, CIN / 32, BATCH), dim3(32, 8)>>>(x, XT);

    // EdgeConv 1..4, outputs written into slices of H (ld = 1152)
    run_edgeconv(0, XT,      CIN,  768, W1, bn1, 512, H,       HDIM, G, diag, idx, U, V);
    run_edgeconv(1, H,       HDIM, 512, W2, bn2, 256, H + 512, HDIM, G, diag, idx, U, V);
    run_edgeconv(2, H + 512, HDIM, 256, W3, bn3, 128, H + 768, HDIM, G, diag, idx, U, V);
    run_edgeconv(3, H + 768, HDIM, 128, W4, bn4, 256, H + 896, HDIM, G, diag, idx, U, V);

    // conv5 on tensor cores (wmma bf16 split): split H, then GEMM
    split_kernel<<<(MTOT * HDIM + 255) / 256, 256>>>(H, Hhi, Hlo, MTOT * HDIM);
    wmma_conv5_kernel<<<dim3(1024 / 64, MTOT / 128), 256>>>(Hhi, Hlo, Whi, Wlo, bn5, H5);

    // pooling -> pooled (B x 2048)
    pool1_kernel<<<dim3(PCH, BATCH), 256>>>(H5, pmax, psum);
    pool2_kernel<<<dim3(4, BATCH), 256>>>(pmax, psum, pool);

    // head
    head1_kernel<<<dim3(512, BATCH), 256>>>(pool, Wl1, bn6, z);
    head2_kernel<<<dim3(40, BATCH), 128>>>(z, Wl3, bl3, out);
}